// round 9
// baseline (speedup 1.0000x reference)
#include <cuda_runtime.h>
#include <math.h>

// ---------------------------------------------------------------------------
// Problem constants
// ---------------------------------------------------------------------------
#define BB   8      // batch
#define CC   256    // dim
#define HH   40     // pooled height
#define WW   40     // pooled width
#define LL   1600   // tokens per batch (40*40)
#define LLP  1664   // padded token stride (26 * 64)
#define NH   8      // heads
#define HD   32     // head dim
#define HID  1024   // mlp hidden
#define HIRES 160   // low spatial
#define HRES  80    // high spatial

// weight scratch offsets (elements)
#define QW_OFF 0
#define KW_OFF 65536
#define VW_OFF 131072
#define OW_OFF 196608
#define L1_OFF 262144
#define L2_OFF 524288
#define W_TOT  786432

// ---------------------------------------------------------------------------
// Scratch (static __device__ globals; zero-initialized at module load).
// Tail columns [LL, LLP): zeroed by producers or never written (stay 0).
// ---------------------------------------------------------------------------
__device__ float g_posT [CC * LL];
__device__ float g_resid[BB * CC * LLP];
__device__ float g_lowpe_hi[BB * CC * LLP];
__device__ float g_lowpe_lo[BB * CC * LLP];
__device__ float g_highpe_hi[BB * CC * LLP];
__device__ float g_highpe_lo[BB * CC * LLP];
__device__ float g_Q[BB * CC * LLP];
__device__ float g_K[BB * CC * LLP];
__device__ float g_V[BB * CC * LLP];
__device__ float g_qscale[BB * CC];
__device__ float g_kscale[BB * CC];
__device__ float g_KV[BB * NH * HD * HD];
__device__ float g_attn_hi[BB * CC * LLP];   // tails never written -> 0
__device__ float g_attn_lo[BB * CC * LLP];
__device__ float g_o[BB * CC * LLP];
__device__ float g_res2_hi[BB * CC * LLP];   // tails never written -> 0
__device__ float g_res2_lo[BB * CC * LLP];
__device__ float g_h_hi[BB * HID * LLP];
__device__ float g_h_lo[BB * HID * LLP];
__device__ float g_m[BB * CC * LLP];
__device__ float g_final[BB * CC * LLP];
__device__ float g_whi[W_TOT];
__device__ float g_wlo[W_TOT];

// ---------------------------------------------------------------------------
// tf32 helpers (3xTF32 split: x = hi + lo, both tf32-valued; err ~2^-22)
// ---------------------------------------------------------------------------
__device__ __forceinline__ unsigned f2tf(float x) {
    unsigned r;
    asm("cvt.rna.tf32.f32 %0, %1;" : "=r"(r) : "f"(x));
    return r;
}
__device__ __forceinline__ void split_tf(float x, float& h, float& l) {
    h = __uint_as_float(f2tf(x));
    l = __uint_as_float(f2tf(x - h));
}

// warp-level tf32 MMA: D(16x8) += A(16x8,row) * B(8x8,col)
__device__ __forceinline__ void mma8(float* d,
                                     unsigned a0, unsigned a1, unsigned a2, unsigned a3,
                                     unsigned b0, unsigned b1) {
    asm volatile(
        "mma.sync.aligned.m16n8k8.row.col.f32.tf32.tf32.f32 "
        "{%0,%1,%2,%3}, {%4,%5,%6,%7}, {%8,%9}, {%0,%1,%2,%3};\n"
        : "+f"(d[0]), "+f"(d[1]), "+f"(d[2]), "+f"(d[3])
        : "r"(a0), "r"(a1), "r"(a2), "r"(a3), "r"(b0), "r"(b1));
}

// ---------------------------------------------------------------------------
// 0) Weight split prep: g_whi/g_wlo from the six weight matrices
// ---------------------------------------------------------------------------
__global__ void splitw_kernel(const float* __restrict__ qw, const float* __restrict__ kw,
                              const float* __restrict__ vw, const float* __restrict__ ow,
                              const float* __restrict__ l1, const float* __restrict__ l2) {
    int idx = blockIdx.x * 256 + threadIdx.x;
    if (idx >= W_TOT) return;
    float v;
    if      (idx < KW_OFF) v = qw[idx - QW_OFF];
    else if (idx < VW_OFF) v = kw[idx - KW_OFF];
    else if (idx < OW_OFF) v = vw[idx - VW_OFF];
    else if (idx < L1_OFF) v = ow[idx - OW_OFF];
    else if (idx < L2_OFF) v = l1[idx - L1_OFF];
    else                   v = l2[idx - L2_OFF];
    float h, l;
    split_tf(v, h, l);
    g_whi[idx] = h;
    g_wlo[idx] = l;
}

// ---------------------------------------------------------------------------
// 1) Positional embedding, transposed: posT[c][l]
// ---------------------------------------------------------------------------
__global__ void pos_kernel() {
    int idx = blockIdx.x * 256 + threadIdx.x;
    if (idx >= CC * LL) return;
    int c = idx / LL;
    int l = idx % LL;
    int g = c >> 6;
    int j = c & 63;
    float om  = __powf(10000.0f, -(float)j / 64.0f);
    float coord = (g < 2) ? (float)(l / WW) : (float)(l % WW);
    float arg = coord * om;
    g_posT[idx] = (g & 1) ? cosf(arg) : sinf(arg);
}

// ---------------------------------------------------------------------------
// 2) Pooling (padded stride; writes tf32 hi/lo pairs for the GEMM inputs)
// ---------------------------------------------------------------------------
__global__ void pool_low_kernel(const float* __restrict__ low) {
    int bc = blockIdx.x;
    int c  = bc % CC;
    const float* src = low + (size_t)bc * HIRES * HIRES;
    for (int l = threadIdx.x; l < LLP; l += 256) {
        size_t o = (size_t)bc * LLP + l;
        if (l < LL) {
            int ih = l / WW, iw = l % WW;
            float s = 0.f;
            #pragma unroll
            for (int r = 0; r < 4; r++) {
                const float* row = src + (4 * ih + r) * HIRES + 4 * iw;
                s += row[0] + row[1] + row[2] + row[3];
            }
            float m = s * 0.0625f;
            g_resid[o] = m;
            float h, lo2;
            split_tf(m + g_posT[c * LL + l], h, lo2);
            g_lowpe_hi[o] = h;
            g_lowpe_lo[o] = lo2;
        } else {
            g_resid[o] = 0.f;
            g_lowpe_hi[o] = 0.f;
            g_lowpe_lo[o] = 0.f;
        }
    }
}

__global__ void pool_high_kernel(const float* __restrict__ high) {
    int bc = blockIdx.x;
    int c  = bc % CC;
    const float* src = high + (size_t)bc * HRES * HRES;
    for (int l = threadIdx.x; l < LLP; l += 256) {
        size_t o = (size_t)bc * LLP + l;
        if (l < LL) {
            int ih = l / WW, iw = l % WW;
            const float* r0 = src + (2 * ih) * HRES + 2 * iw;
            const float* r1 = r0 + HRES;
            float m = (r0[0] + r0[1] + r1[0] + r1[1]) * 0.25f;
            float h, lo2;
            split_tf(m + g_posT[c * LL + l], h, lo2);
            g_highpe_hi[o] = h;
            g_highpe_lo[o] = lo2;
        } else {
            g_highpe_hi[o] = 0.f;
            g_highpe_lo[o] = 0.f;
        }
    }
}

// ---------------------------------------------------------------------------
// 3) 3xTF32 MMA GEMM: Y[m][l] = sum_k A[m][k] * X[k][l] + bias[m]
//    CTA tile 128(M) x 64(N), k-stage 16, 256 threads = 8 warps (2m x 4n),
//    warp tile 64x16. A,X given as tf32 (hi,lo); D += Ah*Bh + Ah*Bl + Al*Bh.
//    GELU: exact erf epilogue.  SPLIT: store Y as tf32 hi/lo pair.
// ---------------------------------------------------------------------------
struct GSmem {
    float Ah[16][132];
    float Al[16][132];
    float Bh[16][68];
    float Bl[16][68];
};

template<int GELU, int SPLIT>
__device__ __forceinline__ void gemm_mma(
    const float* __restrict__ Ahi, const float* __restrict__ Alo,
    const float* __restrict__ bias,
    const float* __restrict__ Xhi, const float* __restrict__ Xlo,
    float* __restrict__ Yhi, float* __restrict__ Ylo,
    int K, int m0, int n0, GSmem* s)
{
    int tid  = threadIdx.x;
    int lane = tid & 31;
    int warp = tid >> 5;
    int wm = warp & 1, wn = warp >> 1;
    int g = lane >> 2, tig = lane & 3;

    // global staging indices
    int mA = tid >> 1, kqA = (tid & 1) * 8;       // A: 128 m x 16 k
    int kB = tid >> 4, cB4 = (tid & 15) * 4;      // B: 16 k x 64 n

    const float* pAh = Ahi + (size_t)(m0 + mA) * K + kqA;
    const float* pAl = Alo + (size_t)(m0 + mA) * K + kqA;
    const float* pBh = Xhi + (size_t)kB * LLP + n0 + cB4;
    const float* pBl = Xlo + (size_t)kB * LLP + n0 + cB4;

    float acc[4][2][4];
    #pragma unroll
    for (int i = 0; i < 4; i++)
        #pragma unroll
        for (int j = 0; j < 2; j++)
            #pragma unroll
            for (int q = 0; q < 4; q++) acc[i][j][q] = 0.f;

    int nt = K >> 4;

    float4 rah0, rah1, ral0, ral1, rbh, rbl;
    // preload stage 0
    rah0 = *(const float4*)(pAh);     rah1 = *(const float4*)(pAh + 4);
    ral0 = *(const float4*)(pAl);     ral1 = *(const float4*)(pAl + 4);
    rbh  = *(const float4*)(pBh);     rbl  = *(const float4*)(pBl);

    for (int kt = 0; kt < nt; kt++) {
        // regs -> smem
        s->Ah[kqA + 0][mA] = rah0.x; s->Ah[kqA + 1][mA] = rah0.y;
        s->Ah[kqA + 2][mA] = rah0.z; s->Ah[kqA + 3][mA] = rah0.w;
        s->Ah[kqA + 4][mA] = rah1.x; s->Ah[kqA + 5][mA] = rah1.y;
        s->Ah[kqA + 6][mA] = rah1.z; s->Ah[kqA + 7][mA] = rah1.w;
        s->Al[kqA + 0][mA] = ral0.x; s->Al[kqA + 1][mA] = ral0.y;
        s->Al[kqA + 2][mA] = ral0.z; s->Al[kqA + 3][mA] = ral0.w;
        s->Al[kqA + 4][mA] = ral1.x; s->Al[kqA + 5][mA] = ral1.y;
        s->Al[kqA + 6][mA] = ral1.z; s->Al[kqA + 7][mA] = ral1.w;
        *(float4*)&s->Bh[kB][cB4] = rbh;
        *(float4*)&s->Bl[kB][cB4] = rbl;
        __syncthreads();

        if (kt + 1 < nt) {  // prefetch next stage while computing
            int ko = (kt + 1) * 16;
            rah0 = *(const float4*)(pAh + ko);     rah1 = *(const float4*)(pAh + ko + 4);
            ral0 = *(const float4*)(pAl + ko);     ral1 = *(const float4*)(pAl + ko + 4);
            rbh  = *(const float4*)(pBh + (size_t)ko * LLP);
            rbl  = *(const float4*)(pBl + (size_t)ko * LLP);
        }

        #pragma unroll
        for (int k8s = 0; k8s < 16; k8s += 8) {
            unsigned bh[2][2], bl[2][2];
            #pragma unroll
            for (int nb = 0; nb < 2; nb++) {
                int n = wn * 16 + nb * 8 + g;
                bh[nb][0] = __float_as_uint(s->Bh[k8s + tig][n]);
                bh[nb][1] = __float_as_uint(s->Bh[k8s + tig + 4][n]);
                bl[nb][0] = __float_as_uint(s->Bl[k8s + tig][n]);
                bl[nb][1] = __float_as_uint(s->Bl[k8s + tig + 4][n]);
            }
            #pragma unroll
            for (int mb = 0; mb < 4; mb++) {
                int m = wm * 64 + mb * 16 + g;
                unsigned ah0 = __float_as_uint(s->Ah[k8s + tig][m]);
                unsigned ah1 = __float_as_uint(s->Ah[k8s + tig][m + 8]);
                unsigned ah2 = __float_as_uint(s->Ah[k8s + tig + 4][m]);
                unsigned ah3 = __float_as_uint(s->Ah[k8s + tig + 4][m + 8]);
                unsigned al0 = __float_as_uint(s->Al[k8s + tig][m]);
                unsigned al1 = __float_as_uint(s->Al[k8s + tig][m + 8]);
                unsigned al2 = __float_as_uint(s->Al[k8s + tig + 4][m]);
                unsigned al3 = __float_as_uint(s->Al[k8s + tig + 4][m + 8]);
                #pragma unroll
                for (int nb = 0; nb < 2; nb++) {
                    mma8(acc[mb][nb], ah0, ah1, ah2, ah3, bh[nb][0], bh[nb][1]);
                    mma8(acc[mb][nb], ah0, ah1, ah2, ah3, bl[nb][0], bl[nb][1]);
                    mma8(acc[mb][nb], al0, al1, al2, al3, bh[nb][0], bh[nb][1]);
                }
            }
        }
        __syncthreads();
    }

    // epilogue
    #pragma unroll
    for (int mb = 0; mb < 4; mb++) {
        #pragma unroll
        for (int nb = 0; nb < 2; nb++) {
            int row0 = m0 + wm * 64 + mb * 16 + g;
            int row1 = row0 + 8;
            int col  = n0 + wn * 16 + nb * 8 + tig * 2;
            float b0 = bias[row0], b1 = bias[row1];
            float v[4];
            v[0] = acc[mb][nb][0] + b0;
            v[1] = acc[mb][nb][1] + b0;
            v[2] = acc[mb][nb][2] + b1;
            v[3] = acc[mb][nb][3] + b1;
            if (GELU) {
                #pragma unroll
                for (int q = 0; q < 4; q++)
                    v[q] = 0.5f * v[q] * (1.0f + erff(v[q] * 0.70710678118654752f));
            }
            if (SPLIT) {
                float h0, l0, h1, l1, h2, l2, h3, l3;
                split_tf(v[0], h0, l0); split_tf(v[1], h1, l1);
                split_tf(v[2], h2, l2); split_tf(v[3], h3, l3);
                *(float2*)(Yhi + (size_t)row0 * LLP + col) = make_float2(h0, h1);
                *(float2*)(Yhi + (size_t)row1 * LLP + col) = make_float2(h2, h3);
                *(float2*)(Ylo + (size_t)row0 * LLP + col) = make_float2(l0, l1);
                *(float2*)(Ylo + (size_t)row1 * LLP + col) = make_float2(l2, l3);
            } else {
                *(float2*)(Yhi + (size_t)row0 * LLP + col) = make_float2(v[0], v[1]);
                *(float2*)(Yhi + (size_t)row1 * LLP + col) = make_float2(v[2], v[3]);
            }
        }
    }
}

// Fused Q/K/V: gridDim.z = 3*BB
__global__ void __launch_bounds__(256)
qkv_kernel(const float* __restrict__ qb, const float* __restrict__ kb,
           const float* __restrict__ vb) {
    __shared__ GSmem s;
    int sel = blockIdx.z / BB;
    int b   = blockIdx.z % BB;
    const float* Ahi  = g_whi + ((sel == 0) ? QW_OFF : (sel == 1) ? KW_OFF : VW_OFF);
    const float* Alo  = g_wlo + ((sel == 0) ? QW_OFF : (sel == 1) ? KW_OFF : VW_OFF);
    const float* bias = (sel == 0) ? qb : (sel == 1) ? kb : vb;
    const float* Xhi = ((sel == 0) ? g_lowpe_hi : g_highpe_hi) + (size_t)b * CC * LLP;
    const float* Xlo = ((sel == 0) ? g_lowpe_lo : g_highpe_lo) + (size_t)b * CC * LLP;
    float* Y = ((sel == 0) ? g_Q : (sel == 1) ? g_K : g_V) + (size_t)b * CC * LLP;
    gemm_mma<0, 0>(Ahi, Alo, bias, Xhi, Xlo, Y, nullptr, CC,
                   blockIdx.y * 128, blockIdx.x * 64, &s);
}

__global__ void __launch_bounds__(256)
oproj_kernel(const float* __restrict__ ob) {
    __shared__ GSmem s;
    int b = blockIdx.z;
    gemm_mma<0, 0>(g_whi + OW_OFF, g_wlo + OW_OFF, ob,
                   g_attn_hi + (size_t)b * CC * LLP, g_attn_lo + (size_t)b * CC * LLP,
                   g_o + (size_t)b * CC * LLP, nullptr, CC,
                   blockIdx.y * 128, blockIdx.x * 64, &s);
}

__global__ void __launch_bounds__(256)
mlp1_kernel(const float* __restrict__ l1b) {
    __shared__ GSmem s;
    int b = blockIdx.z;
    gemm_mma<1, 1>(g_whi + L1_OFF, g_wlo + L1_OFF, l1b,
                   g_res2_hi + (size_t)b * CC * LLP, g_res2_lo + (size_t)b * CC * LLP,
                   g_h_hi + (size_t)b * HID * LLP, g_h_lo + (size_t)b * HID * LLP, CC,
                   blockIdx.y * 128, blockIdx.x * 64, &s);
}

__global__ void __launch_bounds__(256)
mlp2_kernel(const float* __restrict__ l2b) {
    __shared__ GSmem s;
    int b = blockIdx.z;
    gemm_mma<0, 0>(g_whi + L2_OFF, g_wlo + L2_OFF, l2b,
                   g_h_hi + (size_t)b * HID * LLP, g_h_lo + (size_t)b * HID * LLP,
                   g_m + (size_t)b * CC * LLP, nullptr, HID,
                   blockIdx.y * 128, blockIdx.x * 64, &s);
}

// ---------------------------------------------------------------------------
// 4) L1-norm scales over sequence
// ---------------------------------------------------------------------------
__global__ void abssum_kernel() {
    int bc = blockIdx.x;
    const float* src = ((blockIdx.y == 0) ? g_Q : g_K) + (size_t)bc * LLP;
    float s = 0.f;
    for (int l = threadIdx.x; l < LL; l += 256) s += fabsf(src[l]);
    __shared__ float red[256];
    red[threadIdx.x] = s;
    __syncthreads();
    for (int o = 128; o > 0; o >>= 1) {
        if (threadIdx.x < o) red[threadIdx.x] += red[threadIdx.x + o];
        __syncthreads();
    }
    if (threadIdx.x == 0) {
        float sc = 1.0f / fmaxf(red[0], 1e-6f);
        ((blockIdx.y == 0) ? g_qscale : g_kscale)[bc] = sc;
    }
}

// ---------------------------------------------------------------------------
// 5) KV[n][d][m] with folded Q/K L1 normalizers
// ---------------------------------------------------------------------------
__global__ void kv_kernel() {
    int n = blockIdx.x;
    int b = n / NH, h = n % NH;
    int chbase = h * HD;
    const float* Kp = g_K + ((size_t)b * CC + chbase) * LLP;
    const float* Vp = g_V + ((size_t)b * CC + chbase) * LLP;

    __shared__ float Ks[32][33], Vs[32][33];
    int row = threadIdx.x / 32, col = threadIdx.x % 32;
    float acc = 0.f;
    for (int l0 = 0; l0 < LL; l0 += 32) {
        Ks[row][col] = Kp[(size_t)row * LLP + l0 + col];
        Vs[row][col] = Vp[(size_t)row * LLP + l0 + col];
        __syncthreads();
        #pragma unroll
        for (int lc = 0; lc < 32; lc++)
            acc = fmaf(Ks[row][lc], Vs[col][lc], acc);
        __syncthreads();
    }
    float sc = g_kscale[b * CC + chbase + row] * g_qscale[b * CC + chbase + row];
    g_KV[((size_t)n * HD + row) * HD + col] = acc * sc;
}

// ---------------------------------------------------------------------------
// 6) attn = Q @ KV, fused RMSNorm over head dim; writes tf32 hi/lo pair
// ---------------------------------------------------------------------------
__global__ void attn_kernel(const float* __restrict__ rms_w) {
    int n  = blockIdx.y;
    int l0 = blockIdx.x * 32;
    int b = n / NH, h = n % NH;
    int chbase = h * HD;

    __shared__ float KVs[32][33], Qs[32][33], S[32][33];
    int row = threadIdx.x / 32, col = threadIdx.x % 32;

    KVs[row][col] = g_KV[((size_t)n * HD + row) * HD + col];
    const float* Qp = g_Q + ((size_t)b * CC + chbase) * LLP;
    Qs[row][col] = Qp[(size_t)row * LLP + l0 + col];
    __syncthreads();

    float acc = 0.f;
    #pragma unroll
    for (int d = 0; d < 32; d++)
        acc = fmaf(Qs[d][col], KVs[d][row], acc);
    S[row][col] = acc;
    __syncthreads();

    float ss = 0.f;
    #pragma unroll
    for (int mm = 0; mm < 32; mm++) { float v = S[mm][col]; ss = fmaf(v, v, ss); }
    float r = rsqrtf(ss * (1.0f / 32.0f) + 1.1920929e-07f);

    float h2, l2;
    split_tf(acc * r * rms_w[row], h2, l2);
    size_t o = ((size_t)b * CC + chbase + row) * LLP + l0 + col;
    g_attn_hi[o] = h2;
    g_attn_lo[o] = l2;
}

// ---------------------------------------------------------------------------
// 7) Token LayerNorm + residual (column LN, channel-major)
//    SRC 0: res2 = resid + LN(o)           (writes tf32 hi/lo pair)
//    SRC 1: final = (res2hi+res2lo) + LN(m) (writes fp32)
// ---------------------------------------------------------------------------
template<int SRC>
__global__ void ln_res_kernel(const float* __restrict__ w, const float* __restrict__ bias) {
    const float* X = (SRC == 0) ? g_o : g_m;

    int b = blockIdx.y;
    int l = blockIdx.x * 256 + threadIdx.x;
    if (l >= LL) return;

    const float* Xb = X + (size_t)b * CC * LLP + l;
    float s = 0.f, ss = 0.f;
    for (int c = 0; c < CC; c++) {
        float v = Xb[(size_t)c * LLP];
        s += v; ss = fmaf(v, v, ss);
    }
    float mean = s * (1.0f / CC);
    float var  = ss * (1.0f / CC) - mean * mean;
    float rstd = rsqrtf(var + 1e-5f);

    size_t base = (size_t)b * CC * LLP + l;
    for (int c = 0; c < CC; c++) {
        float v = Xb[(size_t)c * LLP];
        float normed = (v - mean) * rstd * w[c] + bias[c];
        if (SRC == 0) {
            float r = g_resid[base + (size_t)c * LLP] + normed;
            float h2, l2;
            split_tf(r, h2, l2);
            g_res2_hi[base + (size_t)c * LLP] = h2;
            g_res2_lo[base + (size_t)c * LLP] = l2;
        } else {
            float r = g_res2_hi[base + (size_t)c * LLP]
                    + g_res2_lo[base + (size_t)c * LLP] + normed;
            g_final[base + (size_t)c * LLP] = r;
        }
    }
}

// ---------------------------------------------------------------------------
// 8) Bilinear 4x upsample (half-pixel, clamped) * original low
// ---------------------------------------------------------------------------
__global__ void resize_mul_kernel(const float* __restrict__ low, float* __restrict__ out) {
    int bc = blockIdx.x;
    __shared__ float P[LL];
    const float* Fp = g_final + (size_t)bc * LLP;
    for (int i = threadIdx.x; i < LL; i += 256) P[i] = Fp[i];
    __syncthreads();

    const float* lp = low + (size_t)bc * HIRES * HIRES;
    float*       op = out + (size_t)bc * HIRES * HIRES;
    for (int idx = threadIdx.x; idx < HIRES * HIRES; idx += 256) {
        int y = idx / HIRES, x = idx % HIRES;
        float sy = y * 0.25f - 0.375f;
        float sx = x * 0.25f - 0.375f;
        int y0 = (int)floorf(sy); float fy = sy - y0;
        int x0 = (int)floorf(sx); float fx = sx - x0;
        int y1 = min(y0 + 1, HH - 1); y0 = max(y0, 0);
        int x1 = min(x0 + 1, WW - 1); x0 = max(x0, 0);
        float v00 = P[y0 * WW + x0], v01 = P[y0 * WW + x1];
        float v10 = P[y1 * WW + x0], v11 = P[y1 * WW + x1];
        float v = v00 * (1.f - fy) * (1.f - fx) + v01 * (1.f - fy) * fx
                + v10 * fy * (1.f - fx)         + v11 * fy * fx;
        op[idx] = v * lp[idx];
    }
}

// ---------------------------------------------------------------------------
// Launch
// ---------------------------------------------------------------------------
extern "C" void kernel_launch(void* const* d_in, const int* in_sizes, int n_in,
                              void* d_out, int out_size) {
    const float* low  = (const float*)d_in[0];
    const float* high = (const float*)d_in[1];
    const float* q_w = (const float*)d_in[2];  const float* q_b = (const float*)d_in[3];
    const float* k_w = (const float*)d_in[4];  const float* k_b = (const float*)d_in[5];
    const float* v_w = (const float*)d_in[6];  const float* v_b = (const float*)d_in[7];
    const float* o_w = (const float*)d_in[8];  const float* o_b = (const float*)d_in[9];
    const float* rms_w = (const float*)d_in[10];
    const float* l1_w = (const float*)d_in[11]; const float* l1_b = (const float*)d_in[12];
    const float* l2_w = (const float*)d_in[13]; const float* l2_b = (const float*)d_in[14];
    const float* n1_w = (const float*)d_in[15]; const float* n1_b = (const float*)d_in[16];
    const float* n2_w = (const float*)d_in[17]; const float* n2_b = (const float*)d_in[18];
    float* out = (float*)d_out;

    splitw_kernel<<<(W_TOT + 255) / 256, 256>>>(q_w, k_w, v_w, o_w, l1_w, l2_w);
    pos_kernel<<<(CC * LL + 255) / 256, 256>>>();
    pool_low_kernel <<<BB * CC, 256>>>(low);
    pool_high_kernel<<<BB * CC, 256>>>(high);

    dim3 gQKV(LLP / 64, CC / 128, 3 * BB);      // 26 x 2 x 24
    qkv_kernel<<<gQKV, 256>>>(q_b, k_b, v_b);

    abssum_kernel<<<dim3(BB * CC, 2), 256>>>();
    kv_kernel<<<BB * NH, 1024>>>();
    attn_kernel<<<dim3(LL / 32, BB * NH), 1024>>>(rms_w);

    dim3 gP(LLP / 64, CC / 128, BB);            // 26 x 2 x 8
    oproj_kernel<<<gP, 256>>>(o_b);
    ln_res_kernel<0><<<dim3((LL + 255) / 256, BB), 256>>>(n1_w, n1_b);

    dim3 gH(LLP / 64, HID / 128, BB);           // 26 x 8 x 8
    mlp1_kernel<<<gH, 256>>>(l1_b);
    mlp2_kernel<<<gP, 256>>>(l2_b);
    ln_res_kernel<1><<<dim3((LL + 255) / 256, BB), 256>>>(n2_w, n2_b);

    resize_mul_kernel<<<BB * CC, 256>>>(low, out);
}

// round 11
// speedup vs baseline: 1.2897x; 1.2897x over previous
#include <cuda_runtime.h>
#include <math.h>

// ---------------------------------------------------------------------------
// Problem constants
// ---------------------------------------------------------------------------
#define BB   8      // batch
#define CC   256    // dim
#define HH   40     // pooled height
#define WW   40     // pooled width
#define LL   1600   // tokens per batch (40*40)
#define LLP  1664   // padded token stride (26 * 64)
#define NH   8      // heads
#define HD   32     // head dim
#define HID  1024   // mlp hidden
#define HIRES 160   // low spatial
#define HRES  80    // high spatial

// ---------------------------------------------------------------------------
// Scratch (static __device__ globals; zero-initialized at module load).
// Tail columns [LL, LLP): zeroed by producers or never written (stay 0);
// finite garbage flows column-locally only and is never read as output.
// ---------------------------------------------------------------------------
__device__ float g_posT [CC * LL];
__device__ float g_resid[BB * CC * LLP];
__device__ float g_lowpe[BB * CC * LLP];
__device__ float g_highpe[BB * CC * LLP];
__device__ float g_Q[BB * CC * LLP];
__device__ float g_K[BB * CC * LLP];
__device__ float g_V[BB * CC * LLP];
__device__ float g_qscale[BB * CC];
__device__ float g_kscale[BB * CC];
__device__ float g_KV[BB * NH * HD * HD];
__device__ float g_attn[BB * CC * LLP];   // tails never written -> 0
__device__ float g_o[BB * CC * LLP];
__device__ float g_res2[BB * CC * LLP];   // tails never written -> 0
__device__ float g_h[BB * HID * LLP];
__device__ float g_m[BB * CC * LLP];
__device__ float g_final[BB * CC * LLP];

// ---------------------------------------------------------------------------
// tf32 helpers (3xTF32: x = hi + lo, both tf32-valued; operand err ~2^-22)
// ---------------------------------------------------------------------------
__device__ __forceinline__ unsigned f2tf(float x) {
    unsigned r;
    asm("cvt.rna.tf32.f32 %0, %1;" : "=r"(r) : "f"(x));
    return r;
}
__device__ __forceinline__ void split_tf(float x, float& h, float& l) {
    h = __uint_as_float(f2tf(x));
    l = __uint_as_float(f2tf(x - h));
}

// warp-level tf32 MMA: D(16x8) += A(16x8,row) * B(8x8,col)
__device__ __forceinline__ void mma8(float* d,
                                     unsigned a0, unsigned a1, unsigned a2, unsigned a3,
                                     unsigned b0, unsigned b1) {
    asm volatile(
        "mma.sync.aligned.m16n8k8.row.col.f32.tf32.tf32.f32 "
        "{%0,%1,%2,%3}, {%4,%5,%6,%7}, {%8,%9}, {%0,%1,%2,%3};\n"
        : "+f"(d[0]), "+f"(d[1]), "+f"(d[2]), "+f"(d[3])
        : "r"(a0), "r"(a1), "r"(a2), "r"(a3), "r"(b0), "r"(b1));
}

// ---------------------------------------------------------------------------
// 1) Positional embedding, transposed: posT[c][l]
// ---------------------------------------------------------------------------
__global__ void pos_kernel() {
    int idx = blockIdx.x * 256 + threadIdx.x;
    if (idx >= CC * LL) return;
    int c = idx / LL;
    int l = idx % LL;
    int g = c >> 6;
    int j = c & 63;
    float om  = __powf(10000.0f, -(float)j / 64.0f);
    float coord = (g < 2) ? (float)(l / WW) : (float)(l % WW);
    float arg = coord * om;
    g_posT[idx] = (g & 1) ? cosf(arg) : sinf(arg);
}

// ---------------------------------------------------------------------------
// 2) Pooling (fp32 outputs, padded stride, zero tails)
// ---------------------------------------------------------------------------
__global__ void pool_low_kernel(const float* __restrict__ low) {
    int bc = blockIdx.x;
    int c  = bc % CC;
    const float* src = low + (size_t)bc * HIRES * HIRES;
    for (int l = threadIdx.x; l < LLP; l += 256) {
        size_t o = (size_t)bc * LLP + l;
        if (l < LL) {
            int ih = l / WW, iw = l % WW;
            float s = 0.f;
            #pragma unroll
            for (int r = 0; r < 4; r++) {
                const float* row = src + (4 * ih + r) * HIRES + 4 * iw;
                s += row[0] + row[1] + row[2] + row[3];
            }
            float m = s * 0.0625f;
            g_resid[o] = m;
            g_lowpe[o] = m + g_posT[c * LL + l];
        } else {
            g_resid[o] = 0.f;
            g_lowpe[o] = 0.f;
        }
    }
}

__global__ void pool_high_kernel(const float* __restrict__ high) {
    int bc = blockIdx.x;
    int c  = bc % CC;
    const float* src = high + (size_t)bc * HRES * HRES;
    for (int l = threadIdx.x; l < LLP; l += 256) {
        size_t o = (size_t)bc * LLP + l;
        if (l < LL) {
            int ih = l / WW, iw = l % WW;
            const float* r0 = src + (2 * ih) * HRES + 2 * iw;
            const float* r1 = r0 + HRES;
            float m = (r0[0] + r0[1] + r1[0] + r1[1]) * 0.25f;
            g_highpe[o] = m + g_posT[c * LL + l];
        } else {
            g_highpe[o] = 0.f;
        }
    }
}

// ---------------------------------------------------------------------------
// 3) 3xTF32 MMA GEMM, swizzled fragment SMEM, split-at-staging.
//    Y[m][l] = sum_k A[m][k] * X[k][l] + bias[m]   (GELU optional)
//    CTA tile 128(M) x 64(N), k-stage 16, 256 thr = 8 warps (2m x 4n),
//    warp tile 64x16.
//    A frag SMEM: [k8][mb(8)][u(32)][reg(4)], u = lane^(lane>>3),
//                 phys reg = logical reg ^ (2*k8)  -> STS conflict-free,
//                 LDS.128 conflict-free (un-rotated at compile time).
//    B frag SMEM: [k8][ng(8) stride 66][lane(32)*2 + reg], ~2-way STS,
//                 LDS.64 conflict-free (offset = ng*66 + 2*lane).
//    D += Ah*Bh + Ah*Bl + Al*Bh.
// ---------------------------------------------------------------------------
struct GSmem {
    float Ah[2048];   // 2 k8 * 8 mb * 32 u * 4 reg
    float Al[2048];
    float Bh[1056];   // 2 k8 * 8 ng * 66
    float Bl[1056];
};

template<int GELU>
__device__ __forceinline__ void gemm_mma(
    const float* __restrict__ A, const float* __restrict__ bias,
    const float* __restrict__ Xb, float* __restrict__ Yb,
    int K, int m0, int n0, GSmem* s)
{
    int tid  = threadIdx.x;
    int lane = tid & 31;
    int warp = tid >> 5;
    int wm = warp & 1, wn = warp >> 1;
    int g = lane >> 2, tig = lane & 3;

    // ---- staging indices ----
    // A: thread covers row mA, one k8 block (kq = 0 or 8)
    int mA = tid >> 1, kq = (tid & 1) * 8;
    int k8A = kq >> 3;                       // 0 or 1
    int mbA = mA >> 4, rA = mA & 15;
    int rr  = rA & 7;
    int rr4 = rr * 4;
    int xr  = rr >> 1;                       // lane_t>>3 for jt<4
    int aFix = k8A * 1024 + mbA * 128 + (rA >> 3);
    // B: thread covers k row kB, n quad cB4..cB4+3
    int kB = tid >> 4, cB4 = (tid & 15) * 4;
    int k8B = kB >> 3, kkB = kB & 7;
    int bBase = k8B * 528 + (cB4 >> 3) * 66 + (cB4 & 7) * 8 + (kkB & 3) * 2 + (kkB >> 2);

    int uL = lane ^ (lane >> 3);             // A-read swizzled unit

    const float* pA = A + (size_t)(m0 + mA) * K + kq;
    const float* pB = Xb + (size_t)kB * LLP + n0 + cB4;

    float acc[4][2][4];
    #pragma unroll
    for (int i = 0; i < 4; i++)
        #pragma unroll
        for (int j = 0; j < 2; j++)
            #pragma unroll
            for (int q = 0; q < 4; q++) acc[i][j][q] = 0.f;

    int nt = K >> 4;

    float a_r[8], b_r[4];
    // preload stage 0
    {
        float4 t0 = *(const float4*)(pA);
        float4 t1 = *(const float4*)(pA + 4);
        a_r[0]=t0.x; a_r[1]=t0.y; a_r[2]=t0.z; a_r[3]=t0.w;
        a_r[4]=t1.x; a_r[5]=t1.y; a_r[6]=t1.z; a_r[7]=t1.w;
        float4 tb = *(const float4*)(pB);
        b_r[0]=tb.x; b_r[1]=tb.y; b_r[2]=tb.z; b_r[3]=tb.w;
    }

    for (int kt = 0; kt < nt; kt++) {
        // split + scatter regs -> fragment SMEM (conflict-free layout)
        #pragma unroll
        for (int j = 0; j < 8; j++) {
            float h, l;
            split_tf(a_r[j], h, l);
            int jt = j & 3, jh = j >> 2;
            int off = aFix + (rr4 + (jt ^ xr)) * 4 + 2 * (jh ^ k8A);
            s->Ah[off] = h;
            s->Al[off] = l;
        }
        #pragma unroll
        for (int q = 0; q < 4; q++) {
            float h, l;
            split_tf(b_r[q], h, l);
            int off = bBase + q * 8;
            s->Bh[off] = h;
            s->Bl[off] = l;
        }
        __syncthreads();

        if (kt + 1 < nt) {  // prefetch next stage
            int ko = (kt + 1) * 16;
            float4 t0 = *(const float4*)(pA + ko);
            float4 t1 = *(const float4*)(pA + ko + 4);
            a_r[0]=t0.x; a_r[1]=t0.y; a_r[2]=t0.z; a_r[3]=t0.w;
            a_r[4]=t1.x; a_r[5]=t1.y; a_r[6]=t1.z; a_r[7]=t1.w;
            float4 tb = *(const float4*)(pB + (size_t)ko * LLP);
            b_r[0]=tb.x; b_r[1]=tb.y; b_r[2]=tb.z; b_r[3]=tb.w;
        }

        #pragma unroll
        for (int k8s = 0; k8s < 2; k8s++) {
            // B fragments: 2 n-blocks per warp
            float2 bh[2], bl[2];
            #pragma unroll
            for (int nb = 0; nb < 2; nb++) {
                int ng = wn * 2 + nb;
                bh[nb] = *(const float2*)&s->Bh[k8s * 528 + ng * 66 + lane * 2];
                bl[nb] = *(const float2*)&s->Bl[k8s * 528 + ng * 66 + lane * 2];
            }
            #pragma unroll
            for (int mb = 0; mb < 4; mb++) {
                int mbi = wm * 4 + mb;
                float4 ahp = *(const float4*)&s->Ah[k8s * 1024 + mbi * 128 + uL * 4];
                float4 alp = *(const float4*)&s->Al[k8s * 1024 + mbi * 128 + uL * 4];
                // un-rotate phys regs: logical r = phys (r ^ 2*k8s)
                unsigned ah0, ah1, ah2, ah3, al0, al1, al2, al3;
                if (k8s == 0) {
                    ah0 = __float_as_uint(ahp.x); ah1 = __float_as_uint(ahp.y);
                    ah2 = __float_as_uint(ahp.z); ah3 = __float_as_uint(ahp.w);
                    al0 = __float_as_uint(alp.x); al1 = __float_as_uint(alp.y);
                    al2 = __float_as_uint(alp.z); al3 = __float_as_uint(alp.w);
                } else {
                    ah0 = __float_as_uint(ahp.z); ah1 = __float_as_uint(ahp.w);
                    ah2 = __float_as_uint(ahp.x); ah3 = __float_as_uint(ahp.y);
                    al0 = __float_as_uint(alp.z); al1 = __float_as_uint(alp.w);
                    al2 = __float_as_uint(alp.x); al3 = __float_as_uint(alp.y);
                }
                #pragma unroll
                for (int nb = 0; nb < 2; nb++) {
                    unsigned b0h = __float_as_uint(bh[nb].x), b1h = __float_as_uint(bh[nb].y);
                    unsigned b0l = __float_as_uint(bl[nb].x), b1l = __float_as_uint(bl[nb].y);
                    mma8(acc[mb][nb], ah0, ah1, ah2, ah3, b0h, b1h);
                    mma8(acc[mb][nb], ah0, ah1, ah2, ah3, b0l, b1l);
                    mma8(acc[mb][nb], al0, al1, al2, al3, b0h, b1h);
                }
            }
        }
        __syncthreads();
    }

    // epilogue
    #pragma unroll
    for (int mb = 0; mb < 4; mb++) {
        #pragma unroll
        for (int nb = 0; nb < 2; nb++) {
            int row0 = m0 + wm * 64 + mb * 16 + g;
            int row1 = row0 + 8;
            int col  = n0 + wn * 16 + nb * 8 + tig * 2;
            float b0 = bias[row0], b1 = bias[row1];
            float v[4];
            v[0] = acc[mb][nb][0] + b0;
            v[1] = acc[mb][nb][1] + b0;
            v[2] = acc[mb][nb][2] + b1;
            v[3] = acc[mb][nb][3] + b1;
            if (GELU) {
                #pragma unroll
                for (int q = 0; q < 4; q++)
                    v[q] = 0.5f * v[q] * (1.0f + erff(v[q] * 0.70710678118654752f));
            }
            *(float2*)(Yb + (size_t)row0 * LLP + col) = make_float2(v[0], v[1]);
            *(float2*)(Yb + (size_t)row1 * LLP + col) = make_float2(v[2], v[3]);
        }
    }
}

// Fused Q/K/V: gridDim.z = 3*BB
__global__ void __launch_bounds__(256)
qkv_kernel(const float* __restrict__ qw, const float* __restrict__ qb,
           const float* __restrict__ kw, const float* __restrict__ kb,
           const float* __restrict__ vw, const float* __restrict__ vb) {
    __shared__ GSmem s;
    int sel = blockIdx.z / BB;
    int b   = blockIdx.z % BB;
    const float* A    = (sel == 0) ? qw : (sel == 1) ? kw : vw;
    const float* bias = (sel == 0) ? qb : (sel == 1) ? kb : vb;
    const float* Xb = ((sel == 0) ? g_lowpe : g_highpe) + (size_t)b * CC * LLP;
    float* Yb = ((sel == 0) ? g_Q : (sel == 1) ? g_K : g_V) + (size_t)b * CC * LLP;
    gemm_mma<0>(A, bias, Xb, Yb, CC, blockIdx.y * 128, blockIdx.x * 64, &s);
}

__global__ void __launch_bounds__(256)
oproj_kernel(const float* __restrict__ ow, const float* __restrict__ ob) {
    __shared__ GSmem s;
    int b = blockIdx.z;
    gemm_mma<0>(ow, ob, g_attn + (size_t)b * CC * LLP,
                g_o + (size_t)b * CC * LLP, CC,
                blockIdx.y * 128, blockIdx.x * 64, &s);
}

__global__ void __launch_bounds__(256)
mlp1_kernel(const float* __restrict__ w, const float* __restrict__ bias) {
    __shared__ GSmem s;
    int b = blockIdx.z;
    gemm_mma<1>(w, bias, g_res2 + (size_t)b * CC * LLP,
                g_h + (size_t)b * HID * LLP, CC,
                blockIdx.y * 128, blockIdx.x * 64, &s);
}

__global__ void __launch_bounds__(256)
mlp2_kernel(const float* __restrict__ w, const float* __restrict__ bias) {
    __shared__ GSmem s;
    int b = blockIdx.z;
    gemm_mma<0>(w, bias, g_h + (size_t)b * HID * LLP,
                g_m + (size_t)b * CC * LLP, HID,
                blockIdx.y * 128, blockIdx.x * 64, &s);
}

// ---------------------------------------------------------------------------
// 4) L1-norm scales over sequence
// ---------------------------------------------------------------------------
__global__ void abssum_kernel() {
    int bc = blockIdx.x;
    const float* src = ((blockIdx.y == 0) ? g_Q : g_K) + (size_t)bc * LLP;
    float s = 0.f;
    for (int l = threadIdx.x; l < LL; l += 256) s += fabsf(src[l]);
    __shared__ float red[256];
    red[threadIdx.x] = s;
    __syncthreads();
    for (int o = 128; o > 0; o >>= 1) {
        if (threadIdx.x < o) red[threadIdx.x] += red[threadIdx.x + o];
        __syncthreads();
    }
    if (threadIdx.x == 0) {
        float sc = 1.0f / fmaxf(red[0], 1e-6f);
        ((blockIdx.y == 0) ? g_qscale : g_kscale)[bc] = sc;
    }
}

// ---------------------------------------------------------------------------
// 5) KV[n][d][m] with folded Q/K L1 normalizers
// ---------------------------------------------------------------------------
__global__ void kv_kernel() {
    int n = blockIdx.x;
    int b = n / NH, h = n % NH;
    int chbase = h * HD;
    const float* Kp = g_K + ((size_t)b * CC + chbase) * LLP;
    const float* Vp = g_V + ((size_t)b * CC + chbase) * LLP;

    __shared__ float Ks[32][33], Vs[32][33];
    int row = threadIdx.x / 32, col = threadIdx.x % 32;
    float acc = 0.f;
    for (int l0 = 0; l0 < LL; l0 += 32) {
        Ks[row][col] = Kp[(size_t)row * LLP + l0 + col];
        Vs[row][col] = Vp[(size_t)row * LLP + l0 + col];
        __syncthreads();
        #pragma unroll
        for (int lc = 0; lc < 32; lc++)
            acc = fmaf(Ks[row][lc], Vs[col][lc], acc);
        __syncthreads();
    }
    float sc = g_kscale[b * CC + chbase + row] * g_qscale[b * CC + chbase + row];
    g_KV[((size_t)n * HD + row) * HD + col] = acc * sc;
}

// ---------------------------------------------------------------------------
// 6) attn = Q @ KV, fused RMSNorm over head dim (fp32 out)
// ---------------------------------------------------------------------------
__global__ void attn_kernel(const float* __restrict__ rms_w) {
    int n  = blockIdx.y;
    int l0 = blockIdx.x * 32;
    int b = n / NH, h = n % NH;
    int chbase = h * HD;

    __shared__ float KVs[32][33], Qs[32][33], S[32][33];
    int row = threadIdx.x / 32, col = threadIdx.x % 32;

    KVs[row][col] = g_KV[((size_t)n * HD + row) * HD + col];
    const float* Qp = g_Q + ((size_t)b * CC + chbase) * LLP;
    Qs[row][col] = Qp[(size_t)row * LLP + l0 + col];
    __syncthreads();

    float acc = 0.f;
    #pragma unroll
    for (int d = 0; d < 32; d++)
        acc = fmaf(Qs[d][col], KVs[d][row], acc);
    S[row][col] = acc;
    __syncthreads();

    float ss = 0.f;
    #pragma unroll
    for (int mm = 0; mm < 32; mm++) { float v = S[mm][col]; ss = fmaf(v, v, ss); }
    float r = rsqrtf(ss * (1.0f / 32.0f) + 1.1920929e-07f);

    g_attn[((size_t)b * CC + chbase + row) * LLP + l0 + col] = acc * r * rms_w[row];
}

// ---------------------------------------------------------------------------
// 7) Token LayerNorm + residual (column LN, channel-major)
// ---------------------------------------------------------------------------
template<int SRC>
__global__ void ln_res_kernel(const float* __restrict__ w, const float* __restrict__ bias) {
    const float* X = (SRC == 0) ? g_o     : g_m;
    const float* R = (SRC == 0) ? g_resid : g_res2;
    float*       Y = (SRC == 0) ? g_res2  : g_final;

    int b = blockIdx.y;
    int l = blockIdx.x * 256 + threadIdx.x;
    if (l >= LL) return;

    const float* Xb = X + (size_t)b * CC * LLP + l;
    float s = 0.f, ss = 0.f;
    for (int c = 0; c < CC; c++) {
        float v = Xb[(size_t)c * LLP];
        s += v; ss = fmaf(v, v, ss);
    }
    float mean = s * (1.0f / CC);
    float var  = ss * (1.0f / CC) - mean * mean;
    float rstd = rsqrtf(var + 1e-5f);

    const float* Rb = R + (size_t)b * CC * LLP + l;
    float*       Yb = Y + (size_t)b * CC * LLP + l;
    for (int c = 0; c < CC; c++) {
        float v = Xb[(size_t)c * LLP];
        Yb[(size_t)c * LLP] = Rb[(size_t)c * LLP] + (v - mean) * rstd * w[c] + bias[c];
    }
}

// ---------------------------------------------------------------------------
// 8) Bilinear 4x upsample (half-pixel, clamped) * original low
// ---------------------------------------------------------------------------
__global__ void resize_mul_kernel(const float* __restrict__ low, float* __restrict__ out) {
    int bc = blockIdx.x;
    __shared__ float P[LL];
    const float* Fp = g_final + (size_t)bc * LLP;
    for (int i = threadIdx.x; i < LL; i += 256) P[i] = Fp[i];
    __syncthreads();

    const float* lp = low + (size_t)bc * HIRES * HIRES;
    float*       op = out + (size_t)bc * HIRES * HIRES;
    for (int idx = threadIdx.x; idx < HIRES * HIRES; idx += 256) {
        int y = idx / HIRES, x = idx % HIRES;
        float sy = y * 0.25f - 0.375f;
        float sx = x * 0.25f - 0.375f;
        int y0 = (int)floorf(sy); float fy = sy - y0;
        int x0 = (int)floorf(sx); float fx = sx - x0;
        int y1 = min(y0 + 1, HH - 1); y0 = max(y0, 0);
        int x1 = min(x0 + 1, WW - 1); x0 = max(x0, 0);
        float v00 = P[y0 * WW + x0], v01 = P[y0 * WW + x1];
        float v10 = P[y1 * WW + x0], v11 = P[y1 * WW + x1];
        float v = v00 * (1.f - fy) * (1.f - fx) + v01 * (1.f - fy) * fx
                + v10 * fy * (1.f - fx)         + v11 * fy * fx;
        op[idx] = v * lp[idx];
    }
}

// ---------------------------------------------------------------------------
// Launch
// ---------------------------------------------------------------------------
extern "C" void kernel_launch(void* const* d_in, const int* in_sizes, int n_in,
                              void* d_out, int out_size) {
    const float* low  = (const float*)d_in[0];
    const float* high = (const float*)d_in[1];
    const float* q_w = (const float*)d_in[2];  const float* q_b = (const float*)d_in[3];
    const float* k_w = (const float*)d_in[4];  const float* k_b = (const float*)d_in[5];
    const float* v_w = (const float*)d_in[6];  const float* v_b = (const float*)d_in[7];
    const float* o_w = (const float*)d_in[8];  const float* o_b = (const float*)d_in[9];
    const float* rms_w = (const float*)d_in[10];
    const float* l1_w = (const float*)d_in[11]; const float* l1_b = (const float*)d_in[12];
    const float* l2_w = (const float*)d_in[13]; const float* l2_b = (const float*)d_in[14];
    const float* n1_w = (const float*)d_in[15]; const float* n1_b = (const float*)d_in[16];
    const float* n2_w = (const float*)d_in[17]; const float* n2_b = (const float*)d_in[18];
    float* out = (float*)d_out;

    pos_kernel<<<(CC * LL + 255) / 256, 256>>>();
    pool_low_kernel <<<BB * CC, 256>>>(low);
    pool_high_kernel<<<BB * CC, 256>>>(high);

    dim3 gQKV(LLP / 64, CC / 128, 3 * BB);      // 26 x 2 x 24
    qkv_kernel<<<gQKV, 256>>>(q_w, q_b, k_w, k_b, v_w, v_b);

    abssum_kernel<<<dim3(BB * CC, 2), 256>>>();
    kv_kernel<<<BB * NH, 1024>>>();
    attn_kernel<<<dim3(LL / 32, BB * NH), 1024>>>(rms_w);

    dim3 gP(LLP / 64, CC / 128, BB);            // 26 x 2 x 8
    oproj_kernel<<<gP, 256>>>(o_w, o_b);
    ln_res_kernel<0><<<dim3((LL + 255) / 256, BB), 256>>>(n1_w, n1_b);

    dim3 gH(LLP / 64, HID / 128, BB);           // 26 x 8 x 8
    mlp1_kernel<<<gH, 256>>>(l1_w, l1_b);
    mlp2_kernel<<<gP, 256>>>(l2_w, l2_b);
    ln_res_kernel<1><<<dim3((LL + 255) / 256, BB), 256>>>(n2_w, n2_b);

    resize_mul_kernel<<<BB * CC, 256>>>(low, out);
}

// round 13
// speedup vs baseline: 1.6310x; 1.2646x over previous
#include <cuda_runtime.h>
#include <cuda_bf16.h>
#include <math.h>

// ---------------------------------------------------------------------------
// Problem constants
// ---------------------------------------------------------------------------
#define BB   8      // batch
#define CC   256    // dim
#define HH   40     // pooled height
#define WW   40     // pooled width
#define LL   1600   // tokens per batch (40*40)
#define LLP  1664   // padded token stride (26 * 64)
#define NH   8      // heads
#define HD   32     // head dim
#define HID  1024   // mlp hidden
#define HIRES 160   // low spatial
#define HRES  80    // high spatial

// ---------------------------------------------------------------------------
// Scratch (static __device__ globals; zero-initialized at module load).
// Tail columns [LL, LLP): zeroed by producers or never written (stay 0);
// finite garbage flows column-locally only and is never read as output.
// ---------------------------------------------------------------------------
__device__ float g_posT [CC * LL];
__device__ float g_resid[BB * CC * LLP];
__device__ float g_lowpe[BB * CC * LLP];
__device__ float g_highpe[BB * CC * LLP];
__device__ float g_Q[BB * CC * LLP];
__device__ float g_K[BB * CC * LLP];
__device__ float g_V[BB * CC * LLP];
__device__ float g_qscale[BB * CC];
__device__ float g_kscale[BB * CC];
__device__ float g_KV[BB * NH * HD * HD];
__device__ float g_attn[BB * CC * LLP];   // tails never written -> 0
__device__ float g_o[BB * CC * LLP];
__device__ float g_res2[BB * CC * LLP];   // tails never written -> 0
__device__ float g_h[BB * HID * LLP];
__device__ float g_m[BB * CC * LLP];
__device__ float g_final[BB * CC * LLP];

// ---------------------------------------------------------------------------
// bf16 2-split helpers: x = hi + lo (hi,lo bf16), repr err ~2^-18.
// Pack pair (x0 -> low half, x1 -> high half) as bf16x2 words.
// ---------------------------------------------------------------------------
__device__ __forceinline__ void split_pack(float x0, float x1,
                                           unsigned& hw, unsigned& lw) {
    __nv_bfloat16 h0 = __float2bfloat16(x0);
    __nv_bfloat16 h1 = __float2bfloat16(x1);
    float l0f = x0 - __bfloat162float(h0);
    float l1f = x1 - __bfloat162float(h1);
    __nv_bfloat162 hp = __halves2bfloat162(h0, h1);          // .x = x0 part (low)
    __nv_bfloat162 lp = __floats2bfloat162_rn(l0f, l1f);     // .x = l0 (low)
    hw = *reinterpret_cast<unsigned*>(&hp);
    lw = *reinterpret_cast<unsigned*>(&lp);
}

// warp-level bf16 MMA: D(16x8) += A(16x16,row) * B(16x8,col)
__device__ __forceinline__ void mma16(float* d,
                                      unsigned a0, unsigned a1, unsigned a2, unsigned a3,
                                      unsigned b0, unsigned b1) {
    asm volatile(
        "mma.sync.aligned.m16n8k16.row.col.f32.bf16.bf16.f32 "
        "{%0,%1,%2,%3}, {%4,%5,%6,%7}, {%8,%9}, {%0,%1,%2,%3};\n"
        : "+f"(d[0]), "+f"(d[1]), "+f"(d[2]), "+f"(d[3])
        : "r"(a0), "r"(a1), "r"(a2), "r"(a3), "r"(b0), "r"(b1));
}

// ---------------------------------------------------------------------------
// 1) Positional embedding, transposed: posT[c][l]
// ---------------------------------------------------------------------------
__global__ void pos_kernel() {
    int idx = blockIdx.x * 256 + threadIdx.x;
    if (idx >= CC * LL) return;
    int c = idx / LL;
    int l = idx % LL;
    int g = c >> 6;
    int j = c & 63;
    float om  = __powf(10000.0f, -(float)j / 64.0f);
    float coord = (g < 2) ? (float)(l / WW) : (float)(l % WW);
    float arg = coord * om;
    g_posT[idx] = (g & 1) ? cosf(arg) : sinf(arg);
}

// ---------------------------------------------------------------------------
// 2) Pooling (fp32 outputs, padded stride, zero tails)
// ---------------------------------------------------------------------------
__global__ void pool_low_kernel(const float* __restrict__ low) {
    int bc = blockIdx.x;
    int c  = bc % CC;
    const float* src = low + (size_t)bc * HIRES * HIRES;
    for (int l = threadIdx.x; l < LLP; l += 256) {
        size_t o = (size_t)bc * LLP + l;
        if (l < LL) {
            int ih = l / WW, iw = l % WW;
            float s = 0.f;
            #pragma unroll
            for (int r = 0; r < 4; r++) {
                const float* row = src + (4 * ih + r) * HIRES + 4 * iw;
                s += row[0] + row[1] + row[2] + row[3];
            }
            float m = s * 0.0625f;
            g_resid[o] = m;
            g_lowpe[o] = m + g_posT[c * LL + l];
        } else {
            g_resid[o] = 0.f;
            g_lowpe[o] = 0.f;
        }
    }
}

__global__ void pool_high_kernel(const float* __restrict__ high) {
    int bc = blockIdx.x;
    int c  = bc % CC;
    const float* src = high + (size_t)bc * HRES * HRES;
    for (int l = threadIdx.x; l < LLP; l += 256) {
        size_t o = (size_t)bc * LLP + l;
        if (l < LL) {
            int ih = l / WW, iw = l % WW;
            const float* r0 = src + (2 * ih) * HRES + 2 * iw;
            const float* r1 = r0 + HRES;
            float m = (r0[0] + r0[1] + r1[0] + r1[1]) * 0.25f;
            g_highpe[o] = m + g_posT[c * LL + l];
        } else {
            g_highpe[o] = 0.f;
        }
    }
}

// ---------------------------------------------------------------------------
// 3) bf16 2-split MMA GEMM (m16n8k16), fragment SMEM, split-at-staging.
//    Y[m][l] = sum_k A[m][k] * X[k][l] + bias[m]   (GELU optional)
//    CTA tile 128(M) x 64(N), k-stage 16, 256 thr = 8 warps (2m x 4n),
//    warp tile 64x16.  D += Ah*Bh + Ah*Bl + Al*Bh  (bf16x2-packed words).
//    A frag: [mb(8)][slot(32) XOR-swizzled][reg(4)], reads LDS.128
//            conflict-free at u = lane ^ ((lane>>2)&3); stores 2-way.
//    B frag: [ng(8) stride 66][2*lane][reg(2)], reads LDS.64 conflict-free;
//            stores 2-way (pad 66 spreads banks).
// ---------------------------------------------------------------------------
struct GSmem {
    unsigned Ah[1024];   // 8 mb * 32 slots * 4 regs
    unsigned Al[1024];
    unsigned Bh[528];    // 8 ng * 66
    unsigned Bl[528];
};

template<int GELU>
__device__ __forceinline__ void gemm_mma(
    const float* __restrict__ A, const float* __restrict__ bias,
    const float* __restrict__ Xb, float* __restrict__ Yb,
    int K, int m0, int n0, GSmem* s)
{
    int tid  = threadIdx.x;
    int lane = tid & 31;
    int warp = tid >> 5;
    int wm = warp & 1, wn = warp >> 1;
    int g = lane >> 2, tig = lane & 3;

    // ---- staging indices ----
    // A: thread covers row mA, k range kq..kq+7 (pairs p = kq/2 + 0..3)
    int mA = tid >> 1, kq = (tid & 1) * 8;
    int rA  = mA & 15;              // row within mb
    int sA  = rA & 7;
    int aFix = (mA >> 4) * 128 + sA * 16 + (rA >> 3) + (tid & 1) * 2; // + (j^(sA&3))*4
    int sx3 = sA & 3;
    // B: thread covers k-pair kp (rows 2kp,2kp+1), cols n2,n2+1
    int iB = tid & 31, kp = tid >> 5;
    int n2 = iB * 2;
    // slot addr for (P=kp, n): (n>>3)*66 + ((n&7)*4 + (kp&3))*2 + (kp>>2)
    int bFix0 = (n2 >> 3) * 66 + (((n2)     & 7) * 4 + (kp & 3)) * 2 + (kp >> 2);
    int bFix1 = ((n2+1) >> 3) * 66 + (((n2+1) & 7) * 4 + (kp & 3)) * 2 + (kp >> 2);

    int uL = lane ^ ((lane >> 2) & 3);   // A-read swizzled slot

    const float* pA  = A  + (size_t)(m0 + mA) * K + kq;
    const float* pB0 = Xb + (size_t)(2 * kp)     * LLP + n0 + n2;
    const float* pB1 = Xb + (size_t)(2 * kp + 1) * LLP + n0 + n2;

    float acc[4][2][4];
    #pragma unroll
    for (int i = 0; i < 4; i++)
        #pragma unroll
        for (int j = 0; j < 2; j++)
            #pragma unroll
            for (int q = 0; q < 4; q++) acc[i][j][q] = 0.f;

    int nt = K >> 4;

    float a_r[8];
    float2 b0_r, b1_r;
    // preload stage 0
    {
        float4 t0 = *(const float4*)(pA);
        float4 t1 = *(const float4*)(pA + 4);
        a_r[0]=t0.x; a_r[1]=t0.y; a_r[2]=t0.z; a_r[3]=t0.w;
        a_r[4]=t1.x; a_r[5]=t1.y; a_r[6]=t1.z; a_r[7]=t1.w;
        b0_r = *(const float2*)(pB0);
        b1_r = *(const float2*)(pB1);
    }

    for (int kt = 0; kt < nt; kt++) {
        // split + pack + scatter regs -> fragment SMEM
        #pragma unroll
        for (int j = 0; j < 4; j++) {            // j = pair index within k8
            unsigned hw, lw;
            split_pack(a_r[2 * j], a_r[2 * j + 1], hw, lw);
            int off = aFix + ((j ^ sx3) << 2);
            s->Ah[off] = hw;
            s->Al[off] = lw;
        }
        {
            unsigned hw0, lw0, hw1, lw1;
            split_pack(b0_r.x, b1_r.x, hw0, lw0);    // n2   : (row2kp, row2kp+1)
            split_pack(b0_r.y, b1_r.y, hw1, lw1);    // n2+1
            s->Bh[bFix0] = hw0;  s->Bl[bFix0] = lw0;
            s->Bh[bFix1] = hw1;  s->Bl[bFix1] = lw1;
        }
        __syncthreads();

        if (kt + 1 < nt) {  // prefetch next stage
            int ko = (kt + 1) * 16;
            float4 t0 = *(const float4*)(pA + ko);
            float4 t1 = *(const float4*)(pA + ko + 4);
            a_r[0]=t0.x; a_r[1]=t0.y; a_r[2]=t0.z; a_r[3]=t0.w;
            a_r[4]=t1.x; a_r[5]=t1.y; a_r[6]=t1.z; a_r[7]=t1.w;
            b0_r = *(const float2*)(pB0 + (size_t)ko * LLP);
            b1_r = *(const float2*)(pB1 + (size_t)ko * LLP);
        }

        // B fragments: 2 n-blocks per warp
        uint2 bh[2], bl[2];
        #pragma unroll
        for (int nb = 0; nb < 2; nb++) {
            int ng = wn * 2 + nb;
            bh[nb] = *(const uint2*)&s->Bh[ng * 66 + lane * 2];
            bl[nb] = *(const uint2*)&s->Bl[ng * 66 + lane * 2];
        }
        #pragma unroll
        for (int mb = 0; mb < 4; mb++) {
            int mbi = wm * 4 + mb;
            uint4 ah = *(const uint4*)&s->Ah[mbi * 128 + uL * 4];
            uint4 al = *(const uint4*)&s->Al[mbi * 128 + uL * 4];
            #pragma unroll
            for (int nb = 0; nb < 2; nb++) {
                mma16(acc[mb][nb], ah.x, ah.y, ah.z, ah.w, bh[nb].x, bh[nb].y);
                mma16(acc[mb][nb], ah.x, ah.y, ah.z, ah.w, bl[nb].x, bl[nb].y);
                mma16(acc[mb][nb], al.x, al.y, al.z, al.w, bh[nb].x, bh[nb].y);
            }
        }
        __syncthreads();
    }

    // epilogue
    #pragma unroll
    for (int mb = 0; mb < 4; mb++) {
        #pragma unroll
        for (int nb = 0; nb < 2; nb++) {
            int row0 = m0 + wm * 64 + mb * 16 + g;
            int row1 = row0 + 8;
            int col  = n0 + wn * 16 + nb * 8 + tig * 2;
            float b0 = bias[row0], b1 = bias[row1];
            float v[4];
            v[0] = acc[mb][nb][0] + b0;
            v[1] = acc[mb][nb][1] + b0;
            v[2] = acc[mb][nb][2] + b1;
            v[3] = acc[mb][nb][3] + b1;
            if (GELU) {
                #pragma unroll
                for (int q = 0; q < 4; q++)
                    v[q] = 0.5f * v[q] * (1.0f + erff(v[q] * 0.70710678118654752f));
            }
            *(float2*)(Yb + (size_t)row0 * LLP + col) = make_float2(v[0], v[1]);
            *(float2*)(Yb + (size_t)row1 * LLP + col) = make_float2(v[2], v[3]);
        }
    }
}

// Fused Q/K/V: gridDim.z = 3*BB
__global__ void __launch_bounds__(256)
qkv_kernel(const float* __restrict__ qw, const float* __restrict__ qb,
           const float* __restrict__ kw, const float* __restrict__ kb,
           const float* __restrict__ vw, const float* __restrict__ vb) {
    __shared__ GSmem s;
    int sel = blockIdx.z / BB;
    int b   = blockIdx.z % BB;
    const float* A    = (sel == 0) ? qw : (sel == 1) ? kw : vw;
    const float* bias = (sel == 0) ? qb : (sel == 1) ? kb : vb;
    const float* Xb = ((sel == 0) ? g_lowpe : g_highpe) + (size_t)b * CC * LLP;
    float* Yb = ((sel == 0) ? g_Q : (sel == 1) ? g_K : g_V) + (size_t)b * CC * LLP;
    gemm_mma<0>(A, bias, Xb, Yb, CC, blockIdx.y * 128, blockIdx.x * 64, &s);
}

__global__ void __launch_bounds__(256)
oproj_kernel(const float* __restrict__ ow, const float* __restrict__ ob) {
    __shared__ GSmem s;
    int b = blockIdx.z;
    gemm_mma<0>(ow, ob, g_attn + (size_t)b * CC * LLP,
                g_o + (size_t)b * CC * LLP, CC,
                blockIdx.y * 128, blockIdx.x * 64, &s);
}

__global__ void __launch_bounds__(256)
mlp1_kernel(const float* __restrict__ w, const float* __restrict__ bias) {
    __shared__ GSmem s;
    int b = blockIdx.z;
    gemm_mma<1>(w, bias, g_res2 + (size_t)b * CC * LLP,
                g_h + (size_t)b * HID * LLP, CC,
                blockIdx.y * 128, blockIdx.x * 64, &s);
}

__global__ void __launch_bounds__(256)
mlp2_kernel(const float* __restrict__ w, const float* __restrict__ bias) {
    __shared__ GSmem s;
    int b = blockIdx.z;
    gemm_mma<0>(w, bias, g_h + (size_t)b * HID * LLP,
                g_m + (size_t)b * CC * LLP, HID,
                blockIdx.y * 128, blockIdx.x * 64, &s);
}

// ---------------------------------------------------------------------------
// 4) L1-norm scales over sequence
// ---------------------------------------------------------------------------
__global__ void abssum_kernel() {
    int bc = blockIdx.x;
    const float* src = ((blockIdx.y == 0) ? g_Q : g_K) + (size_t)bc * LLP;
    float s = 0.f;
    for (int l = threadIdx.x; l < LL; l += 256) s += fabsf(src[l]);
    __shared__ float red[256];
    red[threadIdx.x] = s;
    __syncthreads();
    for (int o = 128; o > 0; o >>= 1) {
        if (threadIdx.x < o) red[threadIdx.x] += red[threadIdx.x + o];
        __syncthreads();
    }
    if (threadIdx.x == 0) {
        float sc = 1.0f / fmaxf(red[0], 1e-6f);
        ((blockIdx.y == 0) ? g_qscale : g_kscale)[bc] = sc;
    }
}

// ---------------------------------------------------------------------------
// 5) KV[n][d][m] with folded Q/K L1 normalizers
// ---------------------------------------------------------------------------
__global__ void kv_kernel() {
    int n = blockIdx.x;
    int b = n / NH, h = n % NH;
    int chbase = h * HD;
    const float* Kp = g_K + ((size_t)b * CC + chbase) * LLP;
    const float* Vp = g_V + ((size_t)b * CC + chbase) * LLP;

    __shared__ float Ks[32][33], Vs[32][33];
    int row = threadIdx.x / 32, col = threadIdx.x % 32;
    float acc = 0.f;
    for (int l0 = 0; l0 < LL; l0 += 32) {
        Ks[row][col] = Kp[(size_t)row * LLP + l0 + col];
        Vs[row][col] = Vp[(size_t)row * LLP + l0 + col];
        __syncthreads();
        #pragma unroll
        for (int lc = 0; lc < 32; lc++)
            acc = fmaf(Ks[row][lc], Vs[col][lc], acc);
        __syncthreads();
    }
    float sc = g_kscale[b * CC + chbase + row] * g_qscale[b * CC + chbase + row];
    g_KV[((size_t)n * HD + row) * HD + col] = acc * sc;
}

// ---------------------------------------------------------------------------
// 6) attn = Q @ KV, fused RMSNorm over head dim (fp32 out)
// ---------------------------------------------------------------------------
__global__ void attn_kernel(const float* __restrict__ rms_w) {
    int n  = blockIdx.y;
    int l0 = blockIdx.x * 32;
    int b = n / NH, h = n % NH;
    int chbase = h * HD;

    __shared__ float KVs[32][33], Qs[32][33], S[32][33];
    int row = threadIdx.x / 32, col = threadIdx.x % 32;

    KVs[row][col] = g_KV[((size_t)n * HD + row) * HD + col];
    const float* Qp = g_Q + ((size_t)b * CC + chbase) * LLP;
    Qs[row][col] = Qp[(size_t)row * LLP + l0 + col];
    __syncthreads();

    float acc = 0.f;
    #pragma unroll
    for (int d = 0; d < 32; d++)
        acc = fmaf(Qs[d][col], KVs[d][row], acc);
    S[row][col] = acc;
    __syncthreads();

    float ss = 0.f;
    #pragma unroll
    for (int mm = 0; mm < 32; mm++) { float v = S[mm][col]; ss = fmaf(v, v, ss); }
    float r = rsqrtf(ss * (1.0f / 32.0f) + 1.1920929e-07f);

    g_attn[((size_t)b * CC + chbase + row) * LLP + l0 + col] = acc * r * rms_w[row];
}

// ---------------------------------------------------------------------------
// 7) Token LayerNorm + residual (column LN, channel-major)
// ---------------------------------------------------------------------------
template<int SRC>
__global__ void ln_res_kernel(const float* __restrict__ w, const float* __restrict__ bias) {
    const float* X = (SRC == 0) ? g_o     : g_m;
    const float* R = (SRC == 0) ? g_resid : g_res2;
    float*       Y = (SRC == 0) ? g_res2  : g_final;

    int b = blockIdx.y;
    int l = blockIdx.x * 256 + threadIdx.x;
    if (l >= LL) return;

    const float* Xb = X + (size_t)b * CC * LLP + l;
    float s = 0.f, ss = 0.f;
    for (int c = 0; c < CC; c++) {
        float v = Xb[(size_t)c * LLP];
        s += v; ss = fmaf(v, v, ss);
    }
    float mean = s * (1.0f / CC);
    float var  = ss * (1.0f / CC) - mean * mean;
    float rstd = rsqrtf(var + 1e-5f);

    const float* Rb = R + (size_t)b * CC * LLP + l;
    float*       Yb = Y + (size_t)b * CC * LLP + l;
    for (int c = 0; c < CC; c++) {
        float v = Xb[(size_t)c * LLP];
        Yb[(size_t)c * LLP] = Rb[(size_t)c * LLP] + (v - mean) * rstd * w[c] + bias[c];
    }
}

// ---------------------------------------------------------------------------
// 8) Bilinear 4x upsample (half-pixel, clamped) * original low
// ---------------------------------------------------------------------------
__global__ void resize_mul_kernel(const float* __restrict__ low, float* __restrict__ out) {
    int bc = blockIdx.x;
    __shared__ float P[LL];
    const float* Fp = g_final + (size_t)bc * LLP;
    for (int i = threadIdx.x; i < LL; i += 256) P[i] = Fp[i];
    __syncthreads();

    const float* lp = low + (size_t)bc * HIRES * HIRES;
    float*       op = out + (size_t)bc * HIRES * HIRES;
    for (int idx = threadIdx.x; idx < HIRES * HIRES; idx += 256) {
        int y = idx / HIRES, x = idx % HIRES;
        float sy = y * 0.25f - 0.375f;
        float sx = x * 0.25f - 0.375f;
        int y0 = (int)floorf(sy); float fy = sy - y0;
        int x0 = (int)floorf(sx); float fx = sx - x0;
        int y1 = min(y0 + 1, HH - 1); y0 = max(y0, 0);
        int x1 = min(x0 + 1, WW - 1); x0 = max(x0, 0);
        float v00 = P[y0 * WW + x0], v01 = P[y0 * WW + x1];
        float v10 = P[y1 * WW + x0], v11 = P[y1 * WW + x1];
        float v = v00 * (1.f - fy) * (1.f - fx) + v01 * (1.f - fy) * fx
                + v10 * fy * (1.f - fx)         + v11 * fy * fx;
        op[idx] = v * lp[idx];
    }
}

// ---------------------------------------------------------------------------
// Launch
// ---------------------------------------------------------------------------
extern "C" void kernel_launch(void* const* d_in, const int* in_sizes, int n_in,
                              void* d_out, int out_size) {
    const float* low  = (const float*)d_in[0];
    const float* high = (const float*)d_in[1];
    const float* q_w = (const float*)d_in[2];  const float* q_b = (const float*)d_in[3];
    const float* k_w = (const float*)d_in[4];  const float* k_b = (const float*)d_in[5];
    const float* v_w = (const float*)d_in[6];  const float* v_b = (const float*)d_in[7];
    const float* o_w = (const float*)d_in[8];  const float* o_b = (const float*)d_in[9];
    const float* rms_w = (const float*)d_in[10];
    const float* l1_w = (const float*)d_in[11]; const float* l1_b = (const float*)d_in[12];
    const float* l2_w = (const float*)d_in[13]; const float* l2_b = (const float*)d_in[14];
    const float* n1_w = (const float*)d_in[15]; const float* n1_b = (const float*)d_in[16];
    const float* n2_w = (const float*)d_in[17]; const float* n2_b = (const float*)d_in[18];
    float* out = (float*)d_out;

    pos_kernel<<<(CC * LL + 255) / 256, 256>>>();
    pool_low_kernel <<<BB * CC, 256>>>(low);
    pool_high_kernel<<<BB * CC, 256>>>(high);

    dim3 gQKV(LLP / 64, CC / 128, 3 * BB);      // 26 x 2 x 24
    qkv_kernel<<<gQKV, 256>>>(q_w, q_b, k_w, k_b, v_w, v_b);

    abssum_kernel<<<dim3(BB * CC, 2), 256>>>();
    kv_kernel<<<BB * NH, 1024>>>();
    attn_kernel<<<dim3(LL / 32, BB * NH), 1024>>>(rms_w);

    dim3 gP(LLP / 64, CC / 128, BB);            // 26 x 2 x 8
    oproj_kernel<<<gP, 256>>>(o_w, o_b);
    ln_res_kernel<0><<<dim3((LL + 255) / 256, BB), 256>>>(n1_w, n1_b);

    dim3 gH(LLP / 64, HID / 128, BB);           // 26 x 8 x 8
    mlp1_kernel<<<gH, 256>>>(l1_w, l1_b);
    mlp2_kernel<<<gP, 256>>>(l2_w, l2_b);
    ln_res_kernel<1><<<dim3((LL + 255) / 256, BB), 256>>>(n2_w, n2_b);

    resize_mul_kernel<<<BB * CC, 256>>>(low, out);
}

// round 15
// speedup vs baseline: 1.7080x; 1.0472x over previous
#include <cuda_runtime.h>
#include <cuda_bf16.h>
#include <math.h>

// ---------------------------------------------------------------------------
// Problem constants
// ---------------------------------------------------------------------------
#define BB   8      // batch
#define CC   256    // dim
#define HH   40     // pooled height
#define WW   40     // pooled width
#define LL   1600   // tokens per batch (40*40)
#define LLP  1664   // padded token stride (13 * 128)
#define NH   8      // heads
#define HD   32     // head dim
#define HID  1024   // mlp hidden
#define HIRES 160   // low spatial
#define HRES  80    // high spatial

// ---------------------------------------------------------------------------
// Scratch (static __device__ globals; zero-initialized at module load).
// Tail columns [LL, LLP): zeroed by producers or never written (stay 0);
// finite garbage flows column-locally only and is never read as output.
// ---------------------------------------------------------------------------
__device__ float g_posT [CC * LL];
__device__ float g_resid[BB * CC * LLP];
__device__ float g_lowpe[BB * CC * LLP];
__device__ float g_highpe[BB * CC * LLP];
__device__ float g_Q[BB * CC * LLP];
__device__ float g_K[BB * CC * LLP];
__device__ float g_V[BB * CC * LLP];
__device__ float g_qscale[BB * CC];
__device__ float g_kscale[BB * CC];
__device__ float g_KV[BB * NH * HD * HD];
__device__ float g_attn[BB * CC * LLP];   // tails never written -> 0
__device__ float g_o[BB * CC * LLP];
__device__ float g_res2[BB * CC * LLP];   // tails never written -> 0
__device__ float g_h[BB * HID * LLP];
__device__ float g_m[BB * CC * LLP];
__device__ float g_final[BB * CC * LLP];

// ---------------------------------------------------------------------------
// bf16 2-split helpers: x = hi + lo (hi,lo bf16), repr err ~2^-18.
// Pack pair (x0 -> low half, x1 -> high half) as bf16x2 words.
// ---------------------------------------------------------------------------
__device__ __forceinline__ void split_pack(float x0, float x1,
                                           unsigned& hw, unsigned& lw) {
    __nv_bfloat16 h0 = __float2bfloat16(x0);
    __nv_bfloat16 h1 = __float2bfloat16(x1);
    float l0f = x0 - __bfloat162float(h0);
    float l1f = x1 - __bfloat162float(h1);
    __nv_bfloat162 hp = __halves2bfloat162(h0, h1);
    __nv_bfloat162 lp = __floats2bfloat162_rn(l0f, l1f);
    hw = *reinterpret_cast<unsigned*>(&hp);
    lw = *reinterpret_cast<unsigned*>(&lp);
}

// warp-level bf16 MMA: D(16x8) += A(16x16,row) * B(16x8,col)
__device__ __forceinline__ void mma16(float* d,
                                      unsigned a0, unsigned a1, unsigned a2, unsigned a3,
                                      unsigned b0, unsigned b1) {
    asm volatile(
        "mma.sync.aligned.m16n8k16.row.col.f32.bf16.bf16.f32 "
        "{%0,%1,%2,%3}, {%4,%5,%6,%7}, {%8,%9}, {%0,%1,%2,%3};\n"
        : "+f"(d[0]), "+f"(d[1]), "+f"(d[2]), "+f"(d[3])
        : "r"(a0), "r"(a1), "r"(a2), "r"(a3), "r"(b0), "r"(b1));
}

// ---------------------------------------------------------------------------
// 1) Positional embedding, transposed: posT[c][l]
// ---------------------------------------------------------------------------
__global__ void pos_kernel() {
    int idx = blockIdx.x * 256 + threadIdx.x;
    if (idx >= CC * LL) return;
    int c = idx / LL;
    int l = idx % LL;
    int g = c >> 6;
    int j = c & 63;
    float om  = __powf(10000.0f, -(float)j / 64.0f);
    float coord = (g < 2) ? (float)(l / WW) : (float)(l % WW);
    float arg = coord * om;
    g_posT[idx] = (g & 1) ? cosf(arg) : sinf(arg);
}

// ---------------------------------------------------------------------------
// 2) Pooling (fp32 outputs, padded stride, zero tails)
// ---------------------------------------------------------------------------
__global__ void pool_low_kernel(const float* __restrict__ low) {
    int bc = blockIdx.x;
    int c  = bc % CC;
    const float* src = low + (size_t)bc * HIRES * HIRES;
    for (int l = threadIdx.x; l < LLP; l += 256) {
        size_t o = (size_t)bc * LLP + l;
        if (l < LL) {
            int ih = l / WW, iw = l % WW;
            float s = 0.f;
            #pragma unroll
            for (int r = 0; r < 4; r++) {
                const float* row = src + (4 * ih + r) * HIRES + 4 * iw;
                s += row[0] + row[1] + row[2] + row[3];
            }
            float m = s * 0.0625f;
            g_resid[o] = m;
            g_lowpe[o] = m + g_posT[c * LL + l];
        } else {
            g_resid[o] = 0.f;
            g_lowpe[o] = 0.f;
        }
    }
}

__global__ void pool_high_kernel(const float* __restrict__ high) {
    int bc = blockIdx.x;
    int c  = bc % CC;
    const float* src = high + (size_t)bc * HRES * HRES;
    for (int l = threadIdx.x; l < LLP; l += 256) {
        size_t o = (size_t)bc * LLP + l;
        if (l < LL) {
            int ih = l / WW, iw = l % WW;
            const float* r0 = src + (2 * ih) * HRES + 2 * iw;
            const float* r1 = r0 + HRES;
            float m = (r0[0] + r0[1] + r1[0] + r1[1]) * 0.25f;
            g_highpe[o] = m + g_posT[c * LL + l];
        } else {
            g_highpe[o] = 0.f;
        }
    }
}

// ---------------------------------------------------------------------------
// 3) bf16 2-split MMA GEMM (m16n8k16), fragment SMEM, split-at-staging.
//    Y[m][l] = sum_k A[m][k] * X[k][l] + bias[m]   (GELU optional)
//    CTA tile 128(M) x 128(N), k-stage 16, 256 thr = 8 warps (2m x 4n),
//    warp tile 64x32.  D += Ah*Bh + Ah*Bl + Al*Bh  (bf16x2-packed words).
//    A frag: [mb(8)][slot(32) XOR-swizzled][reg(4)], reads LDS.128
//            conflict-free at u = lane ^ ((lane>>2)&3); stores 2-way.
//    B frag: [ng(16) stride 66][2*lane][reg(2)], reads LDS.64 conflict-free;
//            stores ~2-way (pad 66 spreads banks).
//    bFix(kp,n) = (n>>3)*66 + ((n&7)*4 + (kp&3))*2 + (kp>>2);
//    note bFix(kp+4,n) = bFix(kp,n) + 1  (kp in 0..3).
// ---------------------------------------------------------------------------
struct GSmem {
    unsigned Ah[1024];   // 8 mb * 32 slots * 4 regs
    unsigned Al[1024];
    unsigned Bh[1056];   // 16 ng * 66
    unsigned Bl[1056];
};

template<int GELU>
__device__ __forceinline__ void gemm_mma(
    const float* __restrict__ A, const float* __restrict__ bias,
    const float* __restrict__ Xb, float* __restrict__ Yb,
    int K, int m0, int n0, GSmem* s)
{
    int tid  = threadIdx.x;
    int lane = tid & 31;
    int warp = tid >> 5;
    int wm = warp & 1, wn = warp >> 1;
    int g = lane >> 2, tig = lane & 3;

    // ---- staging indices ----
    // A: thread covers row mA, k range kq..kq+7 (4 bf16x2 pair-words)
    int mA = tid >> 1, kq = (tid & 1) * 8;
    int rA  = mA & 15;
    int sA  = rA & 7;
    int aFix = (mA >> 4) * 128 + sA * 16 + (rA >> 3) + (tid & 1) * 2;
    int sx3 = sA & 3;
    // B: thread covers cols n2,n2+1 at k-pairs kp and kp+4 (kp in 0..3)
    int iB = tid & 63, kp = tid >> 6;            // kp = 0..3
    int n2 = iB * 2;                             // 0..126
    int bFix0 = (n2 >> 3) * 66 + (((n2)     & 7) * 4 + kp) * 2;       // kp>>2 == 0
    int bFix1 = ((n2+1) >> 3) * 66 + (((n2+1) & 7) * 4 + kp) * 2;

    int uL = lane ^ ((lane >> 2) & 3);   // A-read swizzled slot

    const float* pA  = A  + (size_t)(m0 + mA) * K + kq;
    const float* pB0 = Xb + (size_t)(2 * kp)     * LLP + n0 + n2;   // row 2kp
    const float* pB1 = pB0 + LLP;                                    // row 2kp+1
    const float* pB2 = pB0 + 8 * (size_t)LLP;                        // row 2kp+8
    const float* pB3 = pB0 + 9 * (size_t)LLP;                        // row 2kp+9

    float acc[4][4][4];
    #pragma unroll
    for (int i = 0; i < 4; i++)
        #pragma unroll
        for (int j = 0; j < 4; j++)
            #pragma unroll
            for (int q = 0; q < 4; q++) acc[i][j][q] = 0.f;

    int nt = K >> 4;

    float a_r[8];
    float2 b0_r, b1_r, b2_r, b3_r;
    // preload stage 0
    {
        float4 t0 = *(const float4*)(pA);
        float4 t1 = *(const float4*)(pA + 4);
        a_r[0]=t0.x; a_r[1]=t0.y; a_r[2]=t0.z; a_r[3]=t0.w;
        a_r[4]=t1.x; a_r[5]=t1.y; a_r[6]=t1.z; a_r[7]=t1.w;
        b0_r = *(const float2*)(pB0);
        b1_r = *(const float2*)(pB1);
        b2_r = *(const float2*)(pB2);
        b3_r = *(const float2*)(pB3);
    }

    for (int kt = 0; kt < nt; kt++) {
        // split + pack + scatter regs -> fragment SMEM
        #pragma unroll
        for (int j = 0; j < 4; j++) {
            unsigned hw, lw;
            split_pack(a_r[2 * j], a_r[2 * j + 1], hw, lw);
            int off = aFix + ((j ^ sx3) << 2);
            s->Ah[off] = hw;
            s->Al[off] = lw;
        }
        {
            unsigned hw, lw;
            split_pack(b0_r.x, b1_r.x, hw, lw);   // (rows 2kp,2kp+1), col n2
            s->Bh[bFix0] = hw;      s->Bl[bFix0] = lw;
            split_pack(b0_r.y, b1_r.y, hw, lw);   // col n2+1
            s->Bh[bFix1] = hw;      s->Bl[bFix1] = lw;
            split_pack(b2_r.x, b3_r.x, hw, lw);   // (rows 2kp+8,2kp+9), col n2
            s->Bh[bFix0 + 1] = hw;  s->Bl[bFix0 + 1] = lw;
            split_pack(b2_r.y, b3_r.y, hw, lw);   // col n2+1
            s->Bh[bFix1 + 1] = hw;  s->Bl[bFix1 + 1] = lw;
        }
        __syncthreads();

        if (kt + 1 < nt) {  // prefetch next stage
            int ko = (kt + 1) * 16;
            float4 t0 = *(const float4*)(pA + ko);
            float4 t1 = *(const float4*)(pA + ko + 4);
            a_r[0]=t0.x; a_r[1]=t0.y; a_r[2]=t0.z; a_r[3]=t0.w;
            a_r[4]=t1.x; a_r[5]=t1.y; a_r[6]=t1.z; a_r[7]=t1.w;
            size_t koff = (size_t)ko * LLP;
            b0_r = *(const float2*)(pB0 + koff);
            b1_r = *(const float2*)(pB1 + koff);
            b2_r = *(const float2*)(pB2 + koff);
            b3_r = *(const float2*)(pB3 + koff);
        }

        // B fragments: 4 n-blocks per warp
        uint2 bh[4], bl[4];
        #pragma unroll
        for (int nb = 0; nb < 4; nb++) {
            int ng = wn * 4 + nb;
            bh[nb] = *(const uint2*)&s->Bh[ng * 66 + lane * 2];
            bl[nb] = *(const uint2*)&s->Bl[ng * 66 + lane * 2];
        }
        #pragma unroll
        for (int mb = 0; mb < 4; mb++) {
            int mbi = wm * 4 + mb;
            uint4 ah = *(const uint4*)&s->Ah[mbi * 128 + uL * 4];
            uint4 al = *(const uint4*)&s->Al[mbi * 128 + uL * 4];
            #pragma unroll
            for (int nb = 0; nb < 4; nb++) {
                mma16(acc[mb][nb], ah.x, ah.y, ah.z, ah.w, bh[nb].x, bh[nb].y);
                mma16(acc[mb][nb], ah.x, ah.y, ah.z, ah.w, bl[nb].x, bl[nb].y);
                mma16(acc[mb][nb], al.x, al.y, al.z, al.w, bh[nb].x, bh[nb].y);
            }
        }
        __syncthreads();
    }

    // epilogue
    #pragma unroll
    for (int mb = 0; mb < 4; mb++) {
        #pragma unroll
        for (int nb = 0; nb < 4; nb++) {
            int row0 = m0 + wm * 64 + mb * 16 + g;
            int row1 = row0 + 8;
            int col  = n0 + wn * 32 + nb * 8 + tig * 2;
            float b0 = bias[row0], b1 = bias[row1];
            float v[4];
            v[0] = acc[mb][nb][0] + b0;
            v[1] = acc[mb][nb][1] + b0;
            v[2] = acc[mb][nb][2] + b1;
            v[3] = acc[mb][nb][3] + b1;
            if (GELU) {
                #pragma unroll
                for (int q = 0; q < 4; q++)
                    v[q] = 0.5f * v[q] * (1.0f + erff(v[q] * 0.70710678118654752f));
            }
            *(float2*)(Yb + (size_t)row0 * LLP + col) = make_float2(v[0], v[1]);
            *(float2*)(Yb + (size_t)row1 * LLP + col) = make_float2(v[2], v[3]);
        }
    }
}

// Fused Q/K/V: gridDim.z = 3*BB
__global__ void __launch_bounds__(256, 2)
qkv_kernel(const float* __restrict__ qw, const float* __restrict__ qb,
           const float* __restrict__ kw, const float* __restrict__ kb,
           const float* __restrict__ vw, const float* __restrict__ vb) {
    __shared__ GSmem s;
    int sel = blockIdx.z / BB;
    int b   = blockIdx.z % BB;
    const float* A    = (sel == 0) ? qw : (sel == 1) ? kw : vw;
    const float* bias = (sel == 0) ? qb : (sel == 1) ? kb : vb;
    const float* Xb = ((sel == 0) ? g_lowpe : g_highpe) + (size_t)b * CC * LLP;
    float* Yb = ((sel == 0) ? g_Q : (sel == 1) ? g_K : g_V) + (size_t)b * CC * LLP;
    gemm_mma<0>(A, bias, Xb, Yb, CC, blockIdx.y * 128, blockIdx.x * 128, &s);
}

__global__ void __launch_bounds__(256, 2)
oproj_kernel(const float* __restrict__ ow, const float* __restrict__ ob) {
    __shared__ GSmem s;
    int b = blockIdx.z;
    gemm_mma<0>(ow, ob, g_attn + (size_t)b * CC * LLP,
                g_o + (size_t)b * CC * LLP, CC,
                blockIdx.y * 128, blockIdx.x * 128, &s);
}

__global__ void __launch_bounds__(256, 2)
mlp1_kernel(const float* __restrict__ w, const float* __restrict__ bias) {
    __shared__ GSmem s;
    int b = blockIdx.z;
    gemm_mma<1>(w, bias, g_res2 + (size_t)b * CC * LLP,
                g_h + (size_t)b * HID * LLP, CC,
                blockIdx.y * 128, blockIdx.x * 128, &s);
}

__global__ void __launch_bounds__(256, 2)
mlp2_kernel(const float* __restrict__ w, const float* __restrict__ bias) {
    __shared__ GSmem s;
    int b = blockIdx.z;
    gemm_mma<0>(w, bias, g_h + (size_t)b * HID * LLP,
                g_m + (size_t)b * CC * LLP, HID,
                blockIdx.y * 128, blockIdx.x * 128, &s);
}

// ---------------------------------------------------------------------------
// 4) L1-norm scales over sequence
// ---------------------------------------------------------------------------
__global__ void abssum_kernel() {
    int bc = blockIdx.x;
    const float* src = ((blockIdx.y == 0) ? g_Q : g_K) + (size_t)bc * LLP;
    float s = 0.f;
    for (int l = threadIdx.x; l < LL; l += 256) s += fabsf(src[l]);
    __shared__ float red[256];
    red[threadIdx.x] = s;
    __syncthreads();
    for (int o = 128; o > 0; o >>= 1) {
        if (threadIdx.x < o) red[threadIdx.x] += red[threadIdx.x + o];
        __syncthreads();
    }
    if (threadIdx.x == 0) {
        float sc = 1.0f / fmaxf(red[0], 1e-6f);
        ((blockIdx.y == 0) ? g_qscale : g_kscale)[bc] = sc;
    }
}

// ---------------------------------------------------------------------------
// 5) KV[n][d][m] with folded Q/K L1 normalizers
// ---------------------------------------------------------------------------
__global__ void kv_kernel() {
    int n = blockIdx.x;
    int b = n / NH, h = n % NH;
    int chbase = h * HD;
    const float* Kp = g_K + ((size_t)b * CC + chbase) * LLP;
    const float* Vp = g_V + ((size_t)b * CC + chbase) * LLP;

    __shared__ float Ks[32][33], Vs[32][33];
    int row = threadIdx.x / 32, col = threadIdx.x % 32;
    float acc = 0.f;
    for (int l0 = 0; l0 < LL; l0 += 32) {
        Ks[row][col] = Kp[(size_t)row * LLP + l0 + col];
        Vs[row][col] = Vp[(size_t)row * LLP + l0 + col];
        __syncthreads();
        #pragma unroll
        for (int lc = 0; lc < 32; lc++)
            acc = fmaf(Ks[row][lc], Vs[col][lc], acc);
        __syncthreads();
    }
    float sc = g_kscale[b * CC + chbase + row] * g_qscale[b * CC + chbase + row];
    g_KV[((size_t)n * HD + row) * HD + col] = acc * sc;
}

// ---------------------------------------------------------------------------
// 6) attn = Q @ KV, fused RMSNorm over head dim (fp32 out)
// ---------------------------------------------------------------------------
__global__ void attn_kernel(const float* __restrict__ rms_w) {
    int n  = blockIdx.y;
    int l0 = blockIdx.x * 32;
    int b = n / NH, h = n % NH;
    int chbase = h * HD;

    __shared__ float KVs[32][33], Qs[32][33], S[32][33];
    int row = threadIdx.x / 32, col = threadIdx.x % 32;

    KVs[row][col] = g_KV[((size_t)n * HD + row) * HD + col];
    const float* Qp = g_Q + ((size_t)b * CC + chbase) * LLP;
    Qs[row][col] = Qp[(size_t)row * LLP + l0 + col];
    __syncthreads();

    float acc = 0.f;
    #pragma unroll
    for (int d = 0; d < 32; d++)
        acc = fmaf(Qs[d][col], KVs[d][row], acc);
    S[row][col] = acc;
    __syncthreads();

    float ss = 0.f;
    #pragma unroll
    for (int mm = 0; mm < 32; mm++) { float v = S[mm][col]; ss = fmaf(v, v, ss); }
    float r = rsqrtf(ss * (1.0f / 32.0f) + 1.1920929e-07f);

    g_attn[((size_t)b * CC + chbase + row) * LLP + l0 + col] = acc * r * rms_w[row];
}

// ---------------------------------------------------------------------------
// 7) Token LayerNorm + residual (column LN, channel-major)
// ---------------------------------------------------------------------------
template<int SRC>
__global__ void ln_res_kernel(const float* __restrict__ w, const float* __restrict__ bias) {
    const float* X = (SRC == 0) ? g_o     : g_m;
    const float* R = (SRC == 0) ? g_resid : g_res2;
    float*       Y = (SRC == 0) ? g_res2  : g_final;

    int b = blockIdx.y;
    int l = blockIdx.x * 256 + threadIdx.x;
    if (l >= LL) return;

    const float* Xb = X + (size_t)b * CC * LLP + l;
    float s = 0.f, ss = 0.f;
    for (int c = 0; c < CC; c++) {
        float v = Xb[(size_t)c * LLP];
        s += v; ss = fmaf(v, v, ss);
    }
    float mean = s * (1.0f / CC);
    float var  = ss * (1.0f / CC) - mean * mean;
    float rstd = rsqrtf(var + 1e-5f);

    const float* Rb = R + (size_t)b * CC * LLP + l;
    float*       Yb = Y + (size_t)b * CC * LLP + l;
    for (int c = 0; c < CC; c++) {
        float v = Xb[(size_t)c * LLP];
        Yb[(size_t)c * LLP] = Rb[(size_t)c * LLP] + (v - mean) * rstd * w[c] + bias[c];
    }
}

// ---------------------------------------------------------------------------
// 8) Bilinear 4x upsample (half-pixel, clamped) * original low
// ---------------------------------------------------------------------------
__global__ void resize_mul_kernel(const float* __restrict__ low, float* __restrict__ out) {
    int bc = blockIdx.x;
    __shared__ float P[LL];
    const float* Fp = g_final + (size_t)bc * LLP;
    for (int i = threadIdx.x; i < LL; i += 256) P[i] = Fp[i];
    __syncthreads();

    const float* lp = low + (size_t)bc * HIRES * HIRES;
    float*       op = out + (size_t)bc * HIRES * HIRES;
    for (int idx = threadIdx.x; idx < HIRES * HIRES; idx += 256) {
        int y = idx / HIRES, x = idx % HIRES;
        float sy = y * 0.25f - 0.375f;
        float sx = x * 0.25f - 0.375f;
        int y0 = (int)floorf(sy); float fy = sy - y0;
        int x0 = (int)floorf(sx); float fx = sx - x0;
        int y1 = min(y0 + 1, HH - 1); y0 = max(y0, 0);
        int x1 = min(x0 + 1, WW - 1); x0 = max(x0, 0);
        float v00 = P[y0 * WW + x0], v01 = P[y0 * WW + x1];
        float v10 = P[y1 * WW + x0], v11 = P[y1 * WW + x1];
        float v = v00 * (1.f - fy) * (1.f - fx) + v01 * (1.f - fy) * fx
                + v10 * fy * (1.f - fx)         + v11 * fy * fx;
        op[idx] = v * lp[idx];
    }
}

// ---------------------------------------------------------------------------
// Launch
// ---------------------------------------------------------------------------
extern "C" void kernel_launch(void* const* d_in, const int* in_sizes, int n_in,
                              void* d_out, int out_size) {
    const float* low  = (const float*)d_in[0];
    const float* high = (const float*)d_in[1];
    const float* q_w = (const float*)d_in[2];  const float* q_b = (const float*)d_in[3];
    const float* k_w = (const float*)d_in[4];  const float* k_b = (const float*)d_in[5];
    const float* v_w = (const float*)d_in[6];  const float* v_b = (const float*)d_in[7];
    const float* o_w = (const float*)d_in[8];  const float* o_b = (const float*)d_in[9];
    const float* rms_w = (const float*)d_in[10];
    const float* l1_w = (const float*)d_in[11]; const float* l1_b = (const float*)d_in[12];
    const float* l2_w = (const float*)d_in[13]; const float* l2_b = (const float*)d_in[14];
    const float* n1_w = (const float*)d_in[15]; const float* n1_b = (const float*)d_in[16];
    const float* n2_w = (const float*)d_in[17]; const float* n2_b = (const float*)d_in[18];
    float* out = (float*)d_out;

    pos_kernel<<<(CC * LL + 255) / 256, 256>>>();
    pool_low_kernel <<<BB * CC, 256>>>(low);
    pool_high_kernel<<<BB * CC, 256>>>(high);

    dim3 gQKV(LLP / 128, CC / 128, 3 * BB);     // 13 x 2 x 24
    qkv_kernel<<<gQKV, 256>>>(q_w, q_b, k_w, k_b, v_w, v_b);

    abssum_kernel<<<dim3(BB * CC, 2), 256>>>();
    kv_kernel<<<BB * NH, 1024>>>();
    attn_kernel<<<dim3(LL / 32, BB * NH), 1024>>>(rms_w);

    dim3 gP(LLP / 128, CC / 128, BB);           // 13 x 2 x 8
    oproj_kernel<<<gP, 256>>>(o_w, o_b);
    ln_res_kernel<0><<<dim3((LL + 255) / 256, BB), 256>>>(n1_w, n1_b);

    dim3 gH(LLP / 128, HID / 128, BB);          // 13 x 8 x 8
    mlp1_kernel<<<gH, 256>>>(l1_w, l1_b);
    mlp2_kernel<<<gP, 256>>>(l2_w, l2_b);
    ln_res_kernel<1><<<dim3((LL + 255) / 256, BB), 256>>>(n2_w, n2_b);

    resize_mul_kernel<<<BB * CC, 256>>>(low, out);
}

// round 16
// speedup vs baseline: 1.8801x; 1.1008x over previous
#include <cuda_runtime.h>
#include <cuda_bf16.h>
#include <math.h>

// ---------------------------------------------------------------------------
// Problem constants
// ---------------------------------------------------------------------------
#define BB   8      // batch
#define CC   256    // dim
#define HH   40     // pooled height
#define WW   40     // pooled width
#define LL   1600   // tokens per batch (40*40)
#define LLP  1664   // padded token stride (13 * 128)
#define NH   8      // heads
#define HD   32     // head dim
#define HID  1024   // mlp hidden
#define HIRES 160   // low spatial
#define HRES  80    // high spatial
#define NCH  10     // kv split-L chunks

// ---------------------------------------------------------------------------
// Scratch (static __device__ globals; zero-initialized at module load).
// Tail columns [LL, LLP): zeroed by producers or never written (stay 0);
// finite garbage flows column-locally only and is never read as output.
// ---------------------------------------------------------------------------
__device__ float g_posT [CC * LL];
__device__ float g_resid[BB * CC * LLP];
__device__ float g_lowpe[BB * CC * LLP];
__device__ float g_highpe[BB * CC * LLP];
__device__ float g_Q[BB * CC * LLP];
__device__ float g_K[BB * CC * LLP];
__device__ float g_V[BB * CC * LLP];
__device__ float g_qscale[BB * CC];
__device__ float g_kscale[BB * CC];
__device__ float g_asum_part[13 * 2 * BB * CC];   // per-(n-tile) |.| row sums
__device__ float g_KVpart[NCH * BB * NH * HD * HD];
__device__ float g_KV[BB * NH * HD * HD];
__device__ float g_attn[BB * CC * LLP];   // tails never written -> 0
__device__ float g_o[BB * CC * LLP];
__device__ float g_res2[BB * CC * LLP];   // tails never written -> 0
__device__ float g_h[BB * HID * LLP];
__device__ float g_m[BB * CC * LLP];
__device__ float g_final[BB * CC * LLP];

// ---------------------------------------------------------------------------
// bf16 2-split helpers: x = hi + lo (hi,lo bf16), repr err ~2^-18.
// ---------------------------------------------------------------------------
__device__ __forceinline__ void split_pack(float x0, float x1,
                                           unsigned& hw, unsigned& lw) {
    __nv_bfloat16 h0 = __float2bfloat16(x0);
    __nv_bfloat16 h1 = __float2bfloat16(x1);
    float l0f = x0 - __bfloat162float(h0);
    float l1f = x1 - __bfloat162float(h1);
    __nv_bfloat162 hp = __halves2bfloat162(h0, h1);
    __nv_bfloat162 lp = __floats2bfloat162_rn(l0f, l1f);
    hw = *reinterpret_cast<unsigned*>(&hp);
    lw = *reinterpret_cast<unsigned*>(&lp);
}

// warp-level bf16 MMA: D(16x8) += A(16x16,row) * B(16x8,col)
__device__ __forceinline__ void mma16(float* d,
                                      unsigned a0, unsigned a1, unsigned a2, unsigned a3,
                                      unsigned b0, unsigned b1) {
    asm volatile(
        "mma.sync.aligned.m16n8k16.row.col.f32.bf16.bf16.f32 "
        "{%0,%1,%2,%3}, {%4,%5,%6,%7}, {%8,%9}, {%0,%1,%2,%3};\n"
        : "+f"(d[0]), "+f"(d[1]), "+f"(d[2]), "+f"(d[3])
        : "r"(a0), "r"(a1), "r"(a2), "r"(a3), "r"(b0), "r"(b1));
}

// ---------------------------------------------------------------------------
// 1) Positional embedding, transposed: posT[c][l]
// ---------------------------------------------------------------------------
__global__ void pos_kernel() {
    int idx = blockIdx.x * 256 + threadIdx.x;
    if (idx >= CC * LL) return;
    int c = idx / LL;
    int l = idx % LL;
    int g = c >> 6;
    int j = c & 63;
    float om  = __powf(10000.0f, -(float)j / 64.0f);
    float coord = (g < 2) ? (float)(l / WW) : (float)(l % WW);
    float arg = coord * om;
    g_posT[idx] = (g & 1) ? cosf(arg) : sinf(arg);
}

// ---------------------------------------------------------------------------
// 2) Pooling (fp32 outputs, padded stride, zero tails, float4 loads)
// ---------------------------------------------------------------------------
__global__ void pool_low_kernel(const float* __restrict__ low) {
    int bc = blockIdx.x;
    int c  = bc % CC;
    const float* src = low + (size_t)bc * HIRES * HIRES;
    for (int l = threadIdx.x; l < LLP; l += 256) {
        size_t o = (size_t)bc * LLP + l;
        if (l < LL) {
            int ih = l / WW, iw = l % WW;
            const float* rbase = src + (4 * ih) * HIRES + 4 * iw;
            float4 r0 = *(const float4*)(rbase);
            float4 r1 = *(const float4*)(rbase + HIRES);
            float4 r2 = *(const float4*)(rbase + 2 * HIRES);
            float4 r3 = *(const float4*)(rbase + 3 * HIRES);
            float m = (r0.x + r0.y + r0.z + r0.w + r1.x + r1.y + r1.z + r1.w +
                       r2.x + r2.y + r2.z + r2.w + r3.x + r3.y + r3.z + r3.w) * 0.0625f;
            g_resid[o] = m;
            g_lowpe[o] = m + g_posT[c * LL + l];
        } else {
            g_resid[o] = 0.f;
            g_lowpe[o] = 0.f;
        }
    }
}

__global__ void pool_high_kernel(const float* __restrict__ high) {
    int bc = blockIdx.x;
    int c  = bc % CC;
    const float* src = high + (size_t)bc * HRES * HRES;
    for (int l = threadIdx.x; l < LLP; l += 256) {
        size_t o = (size_t)bc * LLP + l;
        if (l < LL) {
            int ih = l / WW, iw = l % WW;
            const float* r0 = src + (2 * ih) * HRES + 2 * iw;
            const float* r1 = r0 + HRES;
            float m = (r0[0] + r0[1] + r1[0] + r1[1]) * 0.25f;
            g_highpe[o] = m + g_posT[c * LL + l];
        } else {
            g_highpe[o] = 0.f;
        }
    }
}

// ---------------------------------------------------------------------------
// 3) bf16 2-split MMA GEMM (m16n8k16) — identical mainloop to round-15.
//    Optional fused |.| row-sum epilogue (asum != nullptr): deterministic
//    quad-shuffle + unique-writer SMEM slab + per-(CTA) partial store.
// ---------------------------------------------------------------------------
struct GSmem {
    unsigned Ah[1024];   // 8 mb * 32 slots * 4 regs   (aliased as red[2048] floats
    unsigned Al[1024];   //  in the abs epilogue, after the final sync)
    unsigned Bh[1056];   // 16 ng * 66
    unsigned Bl[1056];
};

template<int GELU>
__device__ __forceinline__ void gemm_mma(
    const float* __restrict__ A, const float* __restrict__ bias,
    const float* __restrict__ Xb, float* __restrict__ Yb,
    int K, int m0, int n0, GSmem* s, float* asum)
{
    int tid  = threadIdx.x;
    int lane = tid & 31;
    int warp = tid >> 5;
    int wm = warp & 1, wn = warp >> 1;
    int g = lane >> 2, tig = lane & 3;

    int mA = tid >> 1, kq = (tid & 1) * 8;
    int rA  = mA & 15;
    int sA  = rA & 7;
    int aFix = (mA >> 4) * 128 + sA * 16 + (rA >> 3) + (tid & 1) * 2;
    int sx3 = sA & 3;
    int iB = tid & 63, kp = tid >> 6;
    int n2 = iB * 2;
    int bFix0 = (n2 >> 3) * 66 + (((n2)     & 7) * 4 + kp) * 2;
    int bFix1 = ((n2+1) >> 3) * 66 + (((n2+1) & 7) * 4 + kp) * 2;

    int uL = lane ^ ((lane >> 2) & 3);

    const float* pA  = A  + (size_t)(m0 + mA) * K + kq;
    const float* pB0 = Xb + (size_t)(2 * kp)     * LLP + n0 + n2;
    const float* pB1 = pB0 + LLP;
    const float* pB2 = pB0 + 8 * (size_t)LLP;
    const float* pB3 = pB0 + 9 * (size_t)LLP;

    float acc[4][4][4];
    #pragma unroll
    for (int i = 0; i < 4; i++)
        #pragma unroll
        for (int j = 0; j < 4; j++)
            #pragma unroll
            for (int q = 0; q < 4; q++) acc[i][j][q] = 0.f;

    int nt = K >> 4;

    float a_r[8];
    float2 b0_r, b1_r, b2_r, b3_r;
    {
        float4 t0 = *(const float4*)(pA);
        float4 t1 = *(const float4*)(pA + 4);
        a_r[0]=t0.x; a_r[1]=t0.y; a_r[2]=t0.z; a_r[3]=t0.w;
        a_r[4]=t1.x; a_r[5]=t1.y; a_r[6]=t1.z; a_r[7]=t1.w;
        b0_r = *(const float2*)(pB0);
        b1_r = *(const float2*)(pB1);
        b2_r = *(const float2*)(pB2);
        b3_r = *(const float2*)(pB3);
    }

    for (int kt = 0; kt < nt; kt++) {
        #pragma unroll
        for (int j = 0; j < 4; j++) {
            unsigned hw, lw;
            split_pack(a_r[2 * j], a_r[2 * j + 1], hw, lw);
            int off = aFix + ((j ^ sx3) << 2);
            s->Ah[off] = hw;
            s->Al[off] = lw;
        }
        {
            unsigned hw, lw;
            split_pack(b0_r.x, b1_r.x, hw, lw);
            s->Bh[bFix0] = hw;      s->Bl[bFix0] = lw;
            split_pack(b0_r.y, b1_r.y, hw, lw);
            s->Bh[bFix1] = hw;      s->Bl[bFix1] = lw;
            split_pack(b2_r.x, b3_r.x, hw, lw);
            s->Bh[bFix0 + 1] = hw;  s->Bl[bFix0 + 1] = lw;
            split_pack(b2_r.y, b3_r.y, hw, lw);
            s->Bh[bFix1 + 1] = hw;  s->Bl[bFix1 + 1] = lw;
        }
        __syncthreads();

        if (kt + 1 < nt) {
            int ko = (kt + 1) * 16;
            float4 t0 = *(const float4*)(pA + ko);
            float4 t1 = *(const float4*)(pA + ko + 4);
            a_r[0]=t0.x; a_r[1]=t0.y; a_r[2]=t0.z; a_r[3]=t0.w;
            a_r[4]=t1.x; a_r[5]=t1.y; a_r[6]=t1.z; a_r[7]=t1.w;
            size_t koff = (size_t)ko * LLP;
            b0_r = *(const float2*)(pB0 + koff);
            b1_r = *(const float2*)(pB1 + koff);
            b2_r = *(const float2*)(pB2 + koff);
            b3_r = *(const float2*)(pB3 + koff);
        }

        uint2 bh[4], bl[4];
        #pragma unroll
        for (int nb = 0; nb < 4; nb++) {
            int ng = wn * 4 + nb;
            bh[nb] = *(const uint2*)&s->Bh[ng * 66 + lane * 2];
            bl[nb] = *(const uint2*)&s->Bl[ng * 66 + lane * 2];
        }
        #pragma unroll
        for (int mb = 0; mb < 4; mb++) {
            int mbi = wm * 4 + mb;
            uint4 ah = *(const uint4*)&s->Ah[mbi * 128 + uL * 4];
            uint4 al = *(const uint4*)&s->Al[mbi * 128 + uL * 4];
            #pragma unroll
            for (int nb = 0; nb < 4; nb++) {
                mma16(acc[mb][nb], ah.x, ah.y, ah.z, ah.w, bh[nb].x, bh[nb].y);
                mma16(acc[mb][nb], ah.x, ah.y, ah.z, ah.w, bl[nb].x, bl[nb].y);
                mma16(acc[mb][nb], al.x, al.y, al.z, al.w, bh[nb].x, bh[nb].y);
            }
        }
        __syncthreads();
    }

    // epilogue (red aliases Ah/Al; safe after the mainloop's trailing sync)
    float* red = reinterpret_cast<float*>(s->Ah);
    #pragma unroll
    for (int mb = 0; mb < 4; mb++) {
        #pragma unroll
        for (int nb = 0; nb < 4; nb++) {
            int row0 = m0 + wm * 64 + mb * 16 + g;
            int row1 = row0 + 8;
            int col  = n0 + wn * 32 + nb * 8 + tig * 2;
            float b0 = bias[row0], b1 = bias[row1];
            float v[4];
            v[0] = acc[mb][nb][0] + b0;
            v[1] = acc[mb][nb][1] + b0;
            v[2] = acc[mb][nb][2] + b1;
            v[3] = acc[mb][nb][3] + b1;
            if (GELU) {
                #pragma unroll
                for (int q = 0; q < 4; q++)
                    v[q] = 0.5f * v[q] * (1.0f + erff(v[q] * 0.70710678118654752f));
            }
            if (asum) {
                float a0 = 0.f, a1 = 0.f;
                if (col < LL) {
                    a0 = fabsf(v[0]) + fabsf(v[1]);
                    a1 = fabsf(v[2]) + fabsf(v[3]);
                }
                a0 += __shfl_down_sync(0xffffffffu, a0, 2, 4);
                a0 += __shfl_down_sync(0xffffffffu, a0, 1, 4);
                a1 += __shfl_down_sync(0xffffffffu, a1, 2, 4);
                a1 += __shfl_down_sync(0xffffffffu, a1, 1, 4);
                if (tig == 0) {
                    int r0l = wm * 64 + mb * 16 + g;
                    int j = wn * 4 + nb;
                    red[r0l * 16 + j]       = a0;   // unique writer per slot
                    red[(r0l + 8) * 16 + j] = a1;
                }
            }
            *(float2*)(Yb + (size_t)row0 * LLP + col) = make_float2(v[0], v[1]);
            *(float2*)(Yb + (size_t)row1 * LLP + col) = make_float2(v[2], v[3]);
        }
    }
    if (asum) {
        __syncthreads();
        if (tid < 128) {
            float ssum = 0.f;
            #pragma unroll
            for (int j = 0; j < 16; j++) ssum += red[tid * 16 + j];
            asum[m0 + tid] = ssum;    // deterministic: one writer per entry
        }
    }
}

// Fused Q/K/V: gridDim.z = 3*BB; Q/K also emit |.| row-sum partials
__global__ void __launch_bounds__(256, 2)
qkv_kernel(const float* __restrict__ qw, const float* __restrict__ qb,
           const float* __restrict__ kw, const float* __restrict__ kb,
           const float* __restrict__ vw, const float* __restrict__ vb) {
    __shared__ GSmem s;
    int sel = blockIdx.z / BB;
    int b   = blockIdx.z % BB;
    const float* A    = (sel == 0) ? qw : (sel == 1) ? kw : vw;
    const float* bias = (sel == 0) ? qb : (sel == 1) ? kb : vb;
    const float* Xb = ((sel == 0) ? g_lowpe : g_highpe) + (size_t)b * CC * LLP;
    float* Yb = ((sel == 0) ? g_Q : (sel == 1) ? g_K : g_V) + (size_t)b * CC * LLP;
    float* asum = (sel < 2)
        ? g_asum_part + (size_t)blockIdx.x * (2 * BB * CC) + sel * (BB * CC) + b * CC
        : nullptr;
    gemm_mma<0>(A, bias, Xb, Yb, CC, blockIdx.y * 128, blockIdx.x * 128, &s, asum);
}

__global__ void __launch_bounds__(256, 2)
oproj_kernel(const float* __restrict__ ow, const float* __restrict__ ob) {
    __shared__ GSmem s;
    int b = blockIdx.z;
    gemm_mma<0>(ow, ob, g_attn + (size_t)b * CC * LLP,
                g_o + (size_t)b * CC * LLP, CC,
                blockIdx.y * 128, blockIdx.x * 128, &s, nullptr);
}

__global__ void __launch_bounds__(256, 2)
mlp1_kernel(const float* __restrict__ w, const float* __restrict__ bias) {
    __shared__ GSmem s;
    int b = blockIdx.z;
    gemm_mma<1>(w, bias, g_res2 + (size_t)b * CC * LLP,
                g_h + (size_t)b * HID * LLP, CC,
                blockIdx.y * 128, blockIdx.x * 128, &s, nullptr);
}

__global__ void __launch_bounds__(256, 2)
mlp2_kernel(const float* __restrict__ w, const float* __restrict__ bias) {
    __shared__ GSmem s;
    int b = blockIdx.z;
    gemm_mma<0>(w, bias, g_h + (size_t)b * HID * LLP,
                g_m + (size_t)b * CC * LLP, HID,
                blockIdx.y * 128, blockIdx.x * 128, &s, nullptr);
}

// ---------------------------------------------------------------------------
// 4) Finalize L1-norm scales from the 13 n-tile partials
// ---------------------------------------------------------------------------
__global__ void finalize_scales_kernel() {
    int idx = blockIdx.x * 256 + threadIdx.x;
    if (idx >= 2 * BB * CC) return;
    float ssum = 0.f;
    #pragma unroll
    for (int p = 0; p < 13; p++) ssum += g_asum_part[p * (2 * BB * CC) + idx];
    float sc = 1.0f / fmaxf(ssum, 1e-6f);
    if (idx < BB * CC) g_qscale[idx] = sc;
    else               g_kscale[idx - BB * CC] = sc;
}

// ---------------------------------------------------------------------------
// 5) KV partials (split-L, deterministic) + reduce with folded scales
// ---------------------------------------------------------------------------
__global__ void kv_part_kernel() {          // grid (BB*NH, NCH), block 1024
    int n  = blockIdx.x;
    int ch = blockIdx.y;
    int b = n / NH, h = n % NH;
    int chbase = h * HD;
    const float* Kp = g_K + ((size_t)b * CC + chbase) * LLP;
    const float* Vp = g_V + ((size_t)b * CC + chbase) * LLP;

    __shared__ float Ks[32][33], Vs[32][33];
    int row = threadIdx.x / 32, col = threadIdx.x % 32;
    float acc = 0.f;
    int lbeg = ch * (LL / NCH), lend = lbeg + (LL / NCH);
    for (int l0 = lbeg; l0 < lend; l0 += 32) {
        Ks[row][col] = Kp[(size_t)row * LLP + l0 + col];
        Vs[row][col] = Vp[(size_t)row * LLP + l0 + col];
        __syncthreads();
        #pragma unroll
        for (int lc = 0; lc < 32; lc++)
            acc = fmaf(Ks[row][lc], Vs[col][lc], acc);
        __syncthreads();
    }
    g_KVpart[((size_t)ch * (BB * NH) + n) * (HD * HD) + row * HD + col] = acc;
}

__global__ void kv_reduce_kernel() {        // grid BB*NH, block 1024
    int n = blockIdx.x;
    int t = threadIdx.x;
    int b = n / NH, h = n % NH;
    int d = t >> 5;                          // row of KV = head-dim index
    float ssum = 0.f;
    #pragma unroll
    for (int ch = 0; ch < NCH; ch++)
        ssum += g_KVpart[((size_t)ch * (BB * NH) + n) * (HD * HD) + t];
    float sc = g_kscale[b * CC + h * HD + d] * g_qscale[b * CC + h * HD + d];
    g_KV[(size_t)n * (HD * HD) + t] = ssum * sc;
}

// ---------------------------------------------------------------------------
// 6) attn = Q @ KV, fused RMSNorm over head dim (fp32 out)
// ---------------------------------------------------------------------------
__global__ void attn_kernel(const float* __restrict__ rms_w) {
    int n  = blockIdx.y;
    int l0 = blockIdx.x * 32;
    int b = n / NH, h = n % NH;
    int chbase = h * HD;

    __shared__ float KVs[32][33], Qs[32][33], S[32][33];
    int row = threadIdx.x / 32, col = threadIdx.x % 32;

    KVs[row][col] = g_KV[((size_t)n * HD + row) * HD + col];
    const float* Qp = g_Q + ((size_t)b * CC + chbase) * LLP;
    Qs[row][col] = Qp[(size_t)row * LLP + l0 + col];
    __syncthreads();

    float acc = 0.f;
    #pragma unroll
    for (int d = 0; d < 32; d++)
        acc = fmaf(Qs[d][col], KVs[d][row], acc);
    S[row][col] = acc;
    __syncthreads();

    float ss = 0.f;
    #pragma unroll
    for (int mm = 0; mm < 32; mm++) { float v = S[mm][col]; ss = fmaf(v, v, ss); }
    float r = rsqrtf(ss * (1.0f / 32.0f) + 1.1920929e-07f);

    g_attn[((size_t)b * CC + chbase + row) * LLP + l0 + col] = acc * r * rms_w[row];
}

// ---------------------------------------------------------------------------
// 7) Token LayerNorm + residual (column LN, channel-major)
// ---------------------------------------------------------------------------
template<int SRC>
__global__ void ln_res_kernel(const float* __restrict__ w, const float* __restrict__ bias) {
    const float* X = (SRC == 0) ? g_o     : g_m;
    const float* R = (SRC == 0) ? g_resid : g_res2;
    float*       Y = (SRC == 0) ? g_res2  : g_final;

    int b = blockIdx.y;
    int l = blockIdx.x * 256 + threadIdx.x;
    if (l >= LL) return;

    const float* Xb = X + (size_t)b * CC * LLP + l;
    float s = 0.f, ss = 0.f;
    for (int c = 0; c < CC; c++) {
        float v = Xb[(size_t)c * LLP];
        s += v; ss = fmaf(v, v, ss);
    }
    float mean = s * (1.0f / CC);
    float var  = ss * (1.0f / CC) - mean * mean;
    float rstd = rsqrtf(var + 1e-5f);

    const float* Rb = R + (size_t)b * CC * LLP + l;
    float*       Yb = Y + (size_t)b * CC * LLP + l;
    for (int c = 0; c < CC; c++) {
        float v = Xb[(size_t)c * LLP];
        Yb[(size_t)c * LLP] = Rb[(size_t)c * LLP] + (v - mean) * rstd * w[c] + bias[c];
    }
}

// ---------------------------------------------------------------------------
// 8) Bilinear 4x upsample (half-pixel, clamped) * original low, float4 I/O
// ---------------------------------------------------------------------------
__global__ void resize_mul_kernel(const float* __restrict__ low, float* __restrict__ out) {
    int bc = blockIdx.x;
    __shared__ float P[LL];
    const float* Fp = g_final + (size_t)bc * LLP;
    for (int i = threadIdx.x; i < LL; i += 256) P[i] = Fp[i];
    __syncthreads();

    const float4* lp4 = (const float4*)(low + (size_t)bc * HIRES * HIRES);
    float4*       op4 = (float4*)(out + (size_t)bc * HIRES * HIRES);
    for (int i4 = threadIdx.x; i4 < (HIRES * HIRES) / 4; i4 += 256) {
        int y  = i4 / (HIRES / 4);
        int x0q = (i4 % (HIRES / 4)) * 4;
        float sy = y * 0.25f - 0.375f;
        int y0 = (int)floorf(sy); float fy = sy - y0;
        int y1 = min(y0 + 1, HH - 1); y0 = max(y0, 0);
        float4 lv = lp4[i4];
        float ov[4];
        const float* lvp = &lv.x;
        #pragma unroll
        for (int q = 0; q < 4; q++) {
            int x = x0q + q;
            float sx = x * 0.25f - 0.375f;
            int x0 = (int)floorf(sx); float fx = sx - x0;
            int x1 = min(x0 + 1, WW - 1); x0 = max(x0, 0);
            float v00 = P[y0 * WW + x0], v01 = P[y0 * WW + x1];
            float v10 = P[y1 * WW + x0], v11 = P[y1 * WW + x1];
            float v = v00 * (1.f - fy) * (1.f - fx) + v01 * (1.f - fy) * fx
                    + v10 * fy * (1.f - fx)         + v11 * fy * fx;
            ov[q] = v * lvp[q];
        }
        op4[i4] = make_float4(ov[0], ov[1], ov[2], ov[3]);
    }
}

// ---------------------------------------------------------------------------
// Launch
// ---------------------------------------------------------------------------
extern "C" void kernel_launch(void* const* d_in, const int* in_sizes, int n_in,
                              void* d_out, int out_size) {
    const float* low  = (const float*)d_in[0];
    const float* high = (const float*)d_in[1];
    const float* q_w = (const float*)d_in[2];  const float* q_b = (const float*)d_in[3];
    const float* k_w = (const float*)d_in[4];  const float* k_b = (const float*)d_in[5];
    const float* v_w = (const float*)d_in[6];  const float* v_b = (const float*)d_in[7];
    const float* o_w = (const float*)d_in[8];  const float* o_b = (const float*)d_in[9];
    const float* rms_w = (const float*)d_in[10];
    const float* l1_w = (const float*)d_in[11]; const float* l1_b = (const float*)d_in[12];
    const float* l2_w = (const float*)d_in[13]; const float* l2_b = (const float*)d_in[14];
    const float* n1_w = (const float*)d_in[15]; const float* n1_b = (const float*)d_in[16];
    const float* n2_w = (const float*)d_in[17]; const float* n2_b = (const float*)d_in[18];
    float* out = (float*)d_out;

    pos_kernel<<<(CC * LL + 255) / 256, 256>>>();
    pool_low_kernel <<<BB * CC, 256>>>(low);
    pool_high_kernel<<<BB * CC, 256>>>(high);

    dim3 gQKV(LLP / 128, CC / 128, 3 * BB);     // 13 x 2 x 24
    qkv_kernel<<<gQKV, 256>>>(q_w, q_b, k_w, k_b, v_w, v_b);

    finalize_scales_kernel<<<(2 * BB * CC + 255) / 256, 256>>>();
    kv_part_kernel<<<dim3(BB * NH, NCH), 1024>>>();
    kv_reduce_kernel<<<BB * NH, 1024>>>();
    attn_kernel<<<dim3(LL / 32, BB * NH), 1024>>>(rms_w);

    dim3 gP(LLP / 128, CC / 128, BB);           // 13 x 2 x 8
    oproj_kernel<<<gP, 256>>>(o_w, o_b);
    ln_res_kernel<0><<<dim3((LL + 255) / 256, BB), 256>>>(n1_w, n1_b);

    dim3 gH(LLP / 128, HID / 128, BB);          // 13 x 8 x 8
    mlp1_kernel<<<gH, 256>>>(l1_w, l1_b);
    mlp2_kernel<<<gP, 256>>>(l2_w, l2_b);
    ln_res_kernel<1><<<dim3((LL + 255) / 256, BB), 256>>>(n2_w, n2_b);

    resize_mul_kernel<<<BB * CC, 256>>>(low, out);
}